// round 8
// baseline (speedup 1.0000x reference)
#include <cuda_runtime.h>
#include <cuda_fp16.h>
#include <stdint.h>
#include <stddef.h>

// ---------------- problem constants ----------------
#define B_    2
#define NQ_   768
#define NK_   768

// ---------------- static scratch ----------------
__device__ float    g_qe [B_*NQ_*96];       // [b,q, c*32+m]
__device__ float    g_ke [B_*NK_*96];
__device__ float    g_Aq [B_*NQ_*128];      // b1 + qi @ W1[0:32]
__device__ uint32_t g_kih[B_*NK_*16];       // [b,k][16] packed fp16 ki (32 vals)
__device__ uint32_t g_W1h[128*52];          // [n][kq] B-tile for A=[dot|dist|ki] (K=96)
__device__ uint32_t g_W2h[64*68];           // [n][kq] half2{W2[2kq][n], W2[2kq+1][n]}

// ---------------- helpers ----------------
__device__ __forceinline__ uint32_t smem_u32(const void* p){
    uint32_t a;
    asm("{ .reg .u64 t; cvta.to.shared.u64 t, %1; cvt.u32.u64 %0, t; }" : "=r"(a) : "l"(p));
    return a;
}
__device__ __forceinline__ float tanh_ap(float x){
    float y; asm("tanh.approx.f32 %0, %1;" : "=f"(y) : "f"(x)); return y;
}
__device__ __forceinline__ float silu_f(float v){
    const float hv = 0.5f * v;
    return fmaf(hv, tanh_ap(hv), hv);          // v * sigmoid(v)
}
__device__ __forceinline__ uint32_t pack2(float a, float b){
    __half2 h = __floats2half2_rn(a, b);
    return *(const uint32_t*)&h;
}
__device__ __forceinline__ void ldmx4(uint32_t* r, uint32_t addr){
    asm volatile("ldmatrix.sync.aligned.m8n8.x4.shared.b16 {%0,%1,%2,%3}, [%4];"
        : "=r"(r[0]), "=r"(r[1]), "=r"(r[2]), "=r"(r[3]) : "r"(addr));
}
__device__ __forceinline__ void mma16816(float* d, const uint32_t* a, uint32_t b0, uint32_t b1){
    asm volatile(
        "mma.sync.aligned.m16n8k16.row.col.f32.f16.f16.f32 "
        "{%0,%1,%2,%3}, {%4,%5,%6,%7}, {%8,%9}, {%0,%1,%2,%3};"
        : "+f"(d[0]), "+f"(d[1]), "+f"(d[2]), "+f"(d[3])
        : "r"(a[0]), "r"(a[1]), "r"(a[2]), "r"(a[3]), "r"(b0), "r"(b1));
}

// ---------------- smem layout (bytes) ----------------
// fp16 tiles: row stride = odd multiple of 16B -> conflict-free ldmatrix.
#define O_W1H 0                 // [128 n][104 k] fp16, stride 208B  = 26624
#define O_W2H 26624             // [ 64 n][136 k] fp16, stride 272B  = 17408
#define O_F   44032             // [256 p][104 k] fp16, stride 208B  = 53248
#define O_KE  97280             // [128][96] fp32 packed             = 49152
#define O_AQ  146432            // [16][128] fp32                    = 8192
#define O_QE  154624            // [16][96] fp32                     = 6144
#define O_B2  160768            // [64] fp32                         = 256
#define SMEM_TOTAL 161024

// =====================================================================
// Kernel P: per-row projections (side 0/1) + weight prep (side 2).
// =====================================================================
__global__ __launch_bounds__(128)
void proj_kernel(const float* __restrict__ q_equi, const float* __restrict__ q_inv,
                 const float* __restrict__ k_equi, const float* __restrict__ k_inv,
                 const float* __restrict__ Wqi, const float* __restrict__ bqi,
                 const float* __restrict__ Wki, const float* __restrict__ bki,
                 const float* __restrict__ Wqe, const float* __restrict__ bqe,
                 const float* __restrict__ Wke, const float* __restrict__ bke,
                 const float* __restrict__ W1,  const float* __restrict__ b1,
                 const float* __restrict__ W2)
{
    const int side = blockIdx.y;
    const int r    = blockIdx.x;           // b*768 + n  (sides 0/1)
    const int tid  = threadIdx.x;

    if (side == 2) {
        const int idx = r * 128 + tid;
        if (idx < 128*52) {
            const int n = idx / 52, kq = idx % 52;
            float a = 0.f, b = 0.f;
            if (kq < 48) {
                const int a0 = 2*kq, a1 = 2*kq + 1;
                const int r0 = (a0 < 64) ? (64 + a0) : (a0 - 32);
                const int r1 = (a1 < 64) ? (64 + a1) : (a1 - 32);
                a = W1[(size_t)r0 * 128 + n];
                b = W1[(size_t)r1 * 128 + n];
            }
            g_W1h[n*52 + kq] = pack2(a, b);
        } else if (idx < 128*52 + 64*68) {
            const int j = idx - 128*52;
            const int n = j / 68, kq = j % 68;
            float a = 0.f, b = 0.f;
            if (kq < 64) {
                a = W2[(size_t)(2*kq    ) * 64 + n];
                b = W2[(size_t)(2*kq + 1) * 64 + n];
            }
            g_W2h[n*68 + kq] = pack2(a, b);
        }
        return;
    }

    const float* xe = side ? k_equi : q_equi;
    const float* xi = side ? k_inv  : q_inv;
    const float* We = side ? Wke : Wqe;
    const float* be = side ? bke : bqe;
    const float* Wi = side ? Wki : Wqi;
    const float* bi = side ? bki : bqi;
    float* oute = side ? g_ke : g_qe;

    __shared__ float sxe[768];
    __shared__ float sxi[256];
    __shared__ float spi[32];

    for (int i = tid; i < 768; i += 128) sxe[i] = xe[(size_t)r * 768 + i];
    for (int i = tid; i < 256; i += 128) sxi[i] = xi[(size_t)r * 256 + i];
    __syncthreads();

    if (tid < 96) {
        const int c = tid >> 5, m = tid & 31;
        float acc = be[m];
        #pragma unroll 4
        for (int d = 0; d < 256; d++)
            acc = fmaf(sxe[c * 256 + d], We[d * 32 + m], acc);
        oute[(size_t)r * 96 + c * 32 + m] = acc;
    } else {
        const int m = tid - 96;
        float acc = bi[m];
        #pragma unroll 4
        for (int d = 0; d < 256; d++)
            acc = fmaf(sxi[d], Wi[d * 32 + m], acc);
        spi[m] = acc;
    }
    __syncthreads();

    if (side) {
        if (tid < 16)
            g_kih[(size_t)r * 16 + tid] = pack2(spi[2*tid], spi[2*tid + 1]);
    } else {
        float acc = b1[tid];
        #pragma unroll
        for (int m = 0; m < 32; m++)
            acc = fmaf(spi[m], W1[m * 128 + tid], acc);
        g_Aq[(size_t)r * 128 + tid] = acc;
    }
}

// =====================================================================
// Kernel B: pairwise kernel.
//   CTA = 16 q-rows x 128 k-rows; 8 passes of (2q x 128k, M=256).
//   Warp M-tile = 32 rows (2 sub-tiles of 16) -> halved B-fragment traffic.
//   GEMM1: A=[dot|dist|ki] (K=96) @ W1h ; epi: +Aq, silu (regs) ; GEMM2 (K=128)
// =====================================================================
__global__ __launch_bounds__(256, 1)
void pair_kernel(const float* __restrict__ b2g, float* __restrict__ out)
{
    extern __shared__ char sm[];
    __half*   sW1h = (__half*)(sm + O_W1H);
    __half*   sW2h = (__half*)(sm + O_W2H);
    __half*   sF   = (__half*)(sm + O_F);
    uint32_t* sFu  = (uint32_t*)(sm + O_F);
    float*    sKE  = (float*)(sm + O_KE);
    float*    sAQ  = (float*)(sm + O_AQ);
    float*    sQE  = (float*)(sm + O_QE);
    float*    sB2  = (float*)(sm + O_B2);

    const int tid = threadIdx.x;
    const int b   = blockIdx.z;
    const int k0  = blockIdx.x * 128;
    const int q0  = blockIdx.y * 16;

    // ---------------- phase 0: one-time loads ----------------
    {   // pre-packed fp16 weights: W1h 1664 f4, W2h 1088 f4
        float4* d1 = (float4*)sW1h; const float4* s1 = (const float4*)g_W1h;
        for (int i = tid; i < 1664; i += 256) d1[i] = s1[i];
        float4* d2 = (float4*)sW2h; const float4* s2 = (const float4*)g_W2h;
        for (int i = tid; i < 1088; i += 256) d2[i] = s2[i];
    }
    {   // ke: packed 96-float rows, 128 rows (3072 f4)
        const float4* src = (const float4*)(g_ke + (size_t)(b * NK_ + k0) * 96);
        float4* dst = (float4*)sKE;
        for (int i = tid; i < 3072; i += 256) dst[i] = src[i];
    }
    {   // ki -> F cols 64..95 (uint32 cols 32..47), rows kk and 128+kk
        for (int i = tid; i < 2048; i += 256) {
            const int kk = i >> 4, c = i & 15;
            const uint32_t v = g_kih[(size_t)(b * NK_ + k0 + kk) * 16 + c];
            sFu[kk * 52 + 32 + c]         = v;
            sFu[(128 + kk) * 52 + 32 + c] = v;
        }
    }
    {   // qe: 16 rows = 384 f4 ; Aq: 16 rows = 512 f4
        for (int i = tid; i < 384; i += 256)
            ((float4*)sQE)[i] = *(const float4*)(g_qe + (size_t)(b * NQ_ + q0) * 96 + i * 4);
        for (int i = tid; i < 512; i += 256)
            ((float4*)sAQ)[i] = *(const float4*)(g_Aq + (size_t)(b * NQ_ + q0) * 128 + i * 4);
        if (tid >= 192 && tid < 256) sB2[tid - 192] = b2g[tid - 192];
    }
    __syncthreads();

    // ---------------- warp/lane geometry ----------------
    const int wid = tid >> 5, lane = tid & 31;
    const int grp = lane >> 2, tig = lane & 3;
    const int mb  = wid * 32;                  // warp M-tile: rows mb..mb+31

    const uint32_t sFb  = smem_u32(sF);
    const uint32_t sW1b = smem_u32(sW1h);
    const uint32_t sW2b = smem_u32(sW2h);

    const int arow = lane & 15;
    const int akof = (lane >> 4) * 16;
    const int brow = (lane & 7) + ((lane >> 4) << 3);
    const int bkof = ((lane >> 3) & 1) * 16;

    // ---------------- pass loop: 8 x (2q x 128k) ----------------
    #pragma unroll 1
    for (int pass = 0; pass < 8; pass++) {
        // ---- feats: dot + dist -> F cols 0..63 (fp16), 256 pairs ----
        #pragma unroll
        for (int it = 0; it < 8; it++) {
            const int g  = tid + it * 256;
            const int p  = g >> 3;             // pair 0..255
            const int m  = (g & 7) * 4;
            const int qq = pass * 2 + (p >> 7), kk = p & 127;
            float4 dot = make_float4(0.f, 0.f, 0.f, 0.f);
            float4 d2  = make_float4(0.f, 0.f, 0.f, 0.f);
            #pragma unroll
            for (int c = 0; c < 3; c++) {
                const float4 a  = *(const float4*)&sQE[qq * 96 + c * 32 + m];
                const float4 bb = *(const float4*)&sKE[kk * 96 + c * 32 + m];
                dot.x = fmaf(a.x, bb.x, dot.x);
                dot.y = fmaf(a.y, bb.y, dot.y);
                dot.z = fmaf(a.z, bb.z, dot.z);
                dot.w = fmaf(a.w, bb.w, dot.w);
                float dx = a.x - bb.x; d2.x = fmaf(dx, dx, d2.x);
                float dy = a.y - bb.y; d2.y = fmaf(dy, dy, d2.y);
                float dz = a.z - bb.z; d2.z = fmaf(dz, dz, d2.z);
                float dw = a.w - bb.w; d2.w = fmaf(dw, dw, d2.w);
            }
            *(__half2*)(sF + p * 104 + m)          = __floats2half2_rn(dot.x, dot.y);
            *(__half2*)(sF + p * 104 + m + 2)      = __floats2half2_rn(dot.z, dot.w);
            *(__half2*)(sF + p * 104 + 32 + m)     = __floats2half2_rn(sqrtf(d2.x), sqrtf(d2.y));
            *(__half2*)(sF + p * 104 + 32 + m + 2) = __floats2half2_rn(sqrtf(d2.z), sqrtf(d2.w));
        }
        __syncthreads();

        // ---- GEMM1: D1[32x128] = F[32x96] @ W1h (2 M-subtiles) ----
        float c1[2][16][4];
        #pragma unroll
        for (int mt = 0; mt < 2; mt++)
            #pragma unroll
            for (int nt = 0; nt < 16; nt++)
                #pragma unroll
                for (int j = 0; j < 4; j++) c1[mt][nt][j] = 0.f;

        #pragma unroll
        for (int ks = 0; ks < 6; ks++) {
            uint32_t a[2][4];
            ldmx4(a[0], sFb + (mb + arow) * 208 + ks * 32 + akof);
            ldmx4(a[1], sFb + (mb + 16 + arow) * 208 + ks * 32 + akof);
            #pragma unroll
            for (int np = 0; np < 8; np++) {
                uint32_t bb[4];
                ldmx4(bb, sW1b + (np * 16 + brow) * 208 + ks * 32 + bkof);
                #pragma unroll
                for (int mt = 0; mt < 2; mt++) {
                    mma16816(c1[mt][np * 2 + 0], a[mt], bb[0], bb[1]);
                    mma16816(c1[mt][np * 2 + 1], a[mt], bb[2], bb[3]);
                }
            }
        }

        // ---- epilogue 1 (regs): +Aq, silu -> GEMM2 A-fragments ----
        uint32_t a2[2][8][4];
        {
            const int qrow = pass * 2 + (wid >> 2);
            #pragma unroll
            for (int kt = 0; kt < 8; kt++) {
                #pragma unroll
                for (int hnt = 0; hnt < 2; hnt++) {
                    const int nt = kt * 2 + hnt;
                    const int f  = nt * 8 + tig * 2;
                    const float aq0 = sAQ[qrow * 128 + f];
                    const float aq1 = sAQ[qrow * 128 + f + 1];
                    #pragma unroll
                    for (int mt = 0; mt < 2; mt++) {
                        const float v0 = silu_f(c1[mt][nt][0] + aq0);
                        const float v1 = silu_f(c1[mt][nt][1] + aq1);
                        const float v2 = silu_f(c1[mt][nt][2] + aq0);
                        const float v3 = silu_f(c1[mt][nt][3] + aq1);
                        a2[mt][kt][hnt * 2 + 0] = pack2(v0, v1);
                        a2[mt][kt][hnt * 2 + 1] = pack2(v2, v3);
                    }
                }
            }
        }

        // ---- GEMM2: D2[32x64] = H[32x128] @ W2 (A from registers) ----
        float c2[2][8][4];
        #pragma unroll
        for (int mt = 0; mt < 2; mt++)
            #pragma unroll
            for (int nt = 0; nt < 8; nt++)
                #pragma unroll
                for (int j = 0; j < 4; j++) c2[mt][nt][j] = 0.f;

        #pragma unroll
        for (int ks = 0; ks < 8; ks++) {
            #pragma unroll
            for (int np = 0; np < 4; np++) {
                uint32_t bb[4];
                ldmx4(bb, sW2b + (np * 16 + brow) * 272 + ks * 32 + bkof);
                #pragma unroll
                for (int mt = 0; mt < 2; mt++) {
                    mma16816(c2[mt][np * 2 + 0], a2[mt][ks], bb[0], bb[1]);
                    mma16816(c2[mt][np * 2 + 1], a2[mt][ks], bb[2], bb[3]);
                }
            }
        }

        // ---- epilogue 2: +b2, store ----
        {
            const int q = q0 + pass * 2 + (wid >> 2);
            #pragma unroll
            for (int mt = 0; mt < 2; mt++) {
                #pragma unroll
                for (int h = 0; h < 2; h++) {
                    const int kk = (wid & 3) * 32 + mt * 16 + grp + h * 8;
                    const size_t base = ((size_t)(b * NQ_ + q) * NK_ + k0 + kk) * 64;
                    #pragma unroll
                    for (int nt = 0; nt < 8; nt++) {
                        const int f = nt * 8 + tig * 2;
                        float2 v;
                        v.x = c2[mt][nt][h * 2 + 0] + sB2[f];
                        v.y = c2[mt][nt][h * 2 + 1] + sB2[f + 1];
                        *(float2*)&out[base + f] = v;
                    }
                }
            }
        }
        __syncthreads();   // F reads done CTA-wide before next pass overwrites
    }
}

// =====================================================================
extern "C" void kernel_launch(void* const* d_in, const int* in_sizes, int n_in,
                              void* d_out, int out_size)
{
    (void)in_sizes; (void)n_in; (void)out_size;
    const float* q_equi = (const float*)d_in[0];
    const float* q_inv  = (const float*)d_in[1];
    const float* k_equi = (const float*)d_in[2];
    const float* k_inv  = (const float*)d_in[3];
    const float* Wqi = (const float*)d_in[4];  const float* bqi = (const float*)d_in[5];
    const float* Wki = (const float*)d_in[6];  const float* bki = (const float*)d_in[7];
    const float* Wqe = (const float*)d_in[8];  const float* bqe = (const float*)d_in[9];
    const float* Wke = (const float*)d_in[10]; const float* bke = (const float*)d_in[11];
    const float* W1  = (const float*)d_in[12]; const float* b1  = (const float*)d_in[13];
    const float* W2  = (const float*)d_in[14]; const float* b2  = (const float*)d_in[15];
    float* out = (float*)d_out;

    cudaFuncSetAttribute(pair_kernel, cudaFuncAttributeMaxDynamicSharedMemorySize, SMEM_TOTAL);

    proj_kernel<<<dim3(B_ * NQ_, 3), 128>>>(q_equi, q_inv, k_equi, k_inv,
                                            Wqi, bqi, Wki, bki,
                                            Wqe, bqe, Wke, bke, W1, b1, W2);
    pair_kernel<<<dim3(NK_ / 128, NQ_ / 16, B_), 256, SMEM_TOTAL>>>(b2, out);
}

// round 9
// speedup vs baseline: 1.0007x; 1.0007x over previous
#include <cuda_runtime.h>
#include <cuda_fp16.h>
#include <stdint.h>
#include <stddef.h>

// ---------------- problem constants ----------------
#define B_    2
#define NQ_   768
#define NK_   768

// ---------------- static scratch ----------------
__device__ float    g_qe [B_*NQ_*96];       // [b,q, c*32+m]
__device__ float    g_ke [B_*NK_*96];
__device__ float    g_Aq [B_*NQ_*128];      // b1 + qi @ W1[0:32]
__device__ uint32_t g_kih[B_*NK_*16];       // [b,k][16] packed fp16 ki (32 vals)
__device__ uint32_t g_W1h[128*52];          // [n][kq] B-tile for A=[dot|dist|ki] (K=96)
__device__ uint32_t g_W2h[64*68];           // [n][kq] half2{W2[2kq][n], W2[2kq+1][n]}

// ---------------- helpers ----------------
__device__ __forceinline__ uint32_t smem_u32(const void* p){
    uint32_t a;
    asm("{ .reg .u64 t; cvta.to.shared.u64 t, %1; cvt.u32.u64 %0, t; }" : "=r"(a) : "l"(p));
    return a;
}
__device__ __forceinline__ float tanh_ap(float x){
    float y; asm("tanh.approx.f32 %0, %1;" : "=f"(y) : "f"(x)); return y;
}
__device__ __forceinline__ float silu_f(float v){
    const float hv = 0.5f * v;
    return fmaf(hv, tanh_ap(hv), hv);          // v * sigmoid(v)
}
__device__ __forceinline__ uint32_t pack2(float a, float b){
    __half2 h = __floats2half2_rn(a, b);
    return *(const uint32_t*)&h;
}
__device__ __forceinline__ void ldmx4(uint32_t* r, uint32_t addr){
    asm volatile("ldmatrix.sync.aligned.m8n8.x4.shared.b16 {%0,%1,%2,%3}, [%4];"
        : "=r"(r[0]), "=r"(r[1]), "=r"(r[2]), "=r"(r[3]) : "r"(addr));
}
__device__ __forceinline__ void mma16816(float* d, const uint32_t* a, uint32_t b0, uint32_t b1){
    asm volatile(
        "mma.sync.aligned.m16n8k16.row.col.f32.f16.f16.f32 "
        "{%0,%1,%2,%3}, {%4,%5,%6,%7}, {%8,%9}, {%0,%1,%2,%3};"
        : "+f"(d[0]), "+f"(d[1]), "+f"(d[2]), "+f"(d[3])
        : "r"(a[0]), "r"(a[1]), "r"(a[2]), "r"(a[3]), "r"(b0), "r"(b1));
}

// ---------------- smem layout (bytes) ----------------
// fp16 tiles: row stride = odd multiple of 16B -> conflict-free ldmatrix.
#define O_W1H 0                 // [128 n][104 k] fp16, stride 208B  = 26624
#define O_W2H 26624             // [ 64 n][136 k] fp16, stride 272B  = 17408
#define O_F   44032             // [256 p][104 k] fp16, stride 208B  = 53248
#define O_KE  97280             // [128][96] fp32 packed             = 49152
#define O_AQ  146432            // [16][128] fp32                    = 8192
#define O_QE  154624            // [16][96] fp32                     = 6144
#define O_B2  160768            // [64] fp32                         = 256
#define SMEM_TOTAL 161024

// =====================================================================
// Kernel P: per-row projections (side 0/1) + weight prep (side 2).
// =====================================================================
__global__ __launch_bounds__(128)
void proj_kernel(const float* __restrict__ q_equi, const float* __restrict__ q_inv,
                 const float* __restrict__ k_equi, const float* __restrict__ k_inv,
                 const float* __restrict__ Wqi, const float* __restrict__ bqi,
                 const float* __restrict__ Wki, const float* __restrict__ bki,
                 const float* __restrict__ Wqe, const float* __restrict__ bqe,
                 const float* __restrict__ Wke, const float* __restrict__ bke,
                 const float* __restrict__ W1,  const float* __restrict__ b1,
                 const float* __restrict__ W2)
{
    const int side = blockIdx.y;
    const int r    = blockIdx.x;           // b*768 + n  (sides 0/1)
    const int tid  = threadIdx.x;

    if (side == 2) {
        const int idx = r * 128 + tid;
        if (idx < 128*52) {
            const int n = idx / 52, kq = idx % 52;
            float a = 0.f, b = 0.f;
            if (kq < 48) {
                const int a0 = 2*kq, a1 = 2*kq + 1;
                const int r0 = (a0 < 64) ? (64 + a0) : (a0 - 32);
                const int r1 = (a1 < 64) ? (64 + a1) : (a1 - 32);
                a = W1[(size_t)r0 * 128 + n];
                b = W1[(size_t)r1 * 128 + n];
            }
            g_W1h[n*52 + kq] = pack2(a, b);
        } else if (idx < 128*52 + 64*68) {
            const int j = idx - 128*52;
            const int n = j / 68, kq = j % 68;
            float a = 0.f, b = 0.f;
            if (kq < 64) {
                a = W2[(size_t)(2*kq    ) * 64 + n];
                b = W2[(size_t)(2*kq + 1) * 64 + n];
            }
            g_W2h[n*68 + kq] = pack2(a, b);
        }
        return;
    }

    const float* xe = side ? k_equi : q_equi;
    const float* xi = side ? k_inv  : q_inv;
    const float* We = side ? Wke : Wqe;
    const float* be = side ? bke : bqe;
    const float* Wi = side ? Wki : Wqi;
    const float* bi = side ? bki : bqi;
    float* oute = side ? g_ke : g_qe;

    __shared__ float sxe[768];
    __shared__ float sxi[256];
    __shared__ float spi[32];

    for (int i = tid; i < 768; i += 128) sxe[i] = xe[(size_t)r * 768 + i];
    for (int i = tid; i < 256; i += 128) sxi[i] = xi[(size_t)r * 256 + i];
    __syncthreads();

    if (tid < 96) {
        const int c = tid >> 5, m = tid & 31;
        float acc = be[m];
        #pragma unroll 4
        for (int d = 0; d < 256; d++)
            acc = fmaf(sxe[c * 256 + d], We[d * 32 + m], acc);
        oute[(size_t)r * 96 + c * 32 + m] = acc;
    } else {
        const int m = tid - 96;
        float acc = bi[m];
        #pragma unroll 4
        for (int d = 0; d < 256; d++)
            acc = fmaf(sxi[d], Wi[d * 32 + m], acc);
        spi[m] = acc;
    }
    __syncthreads();

    if (side) {
        if (tid < 16)
            g_kih[(size_t)r * 16 + tid] = pack2(spi[2*tid], spi[2*tid + 1]);
    } else {
        float acc = b1[tid];
        #pragma unroll
        for (int m = 0; m < 32; m++)
            acc = fmaf(spi[m], W1[m * 128 + tid], acc);
        g_Aq[(size_t)r * 128 + tid] = acc;
    }
}

// =====================================================================
// Kernel B: pairwise kernel.
//   CTA = 16 q-rows x 128 k-rows; 8 passes of (2q x 128k, M=256).
//   Warp M-tile = 32 rows. GEMM1 split over two N=64 halves to cap the
//   register peak (c1-half dies into a2 before the next half starts).
// =====================================================================
__global__ __launch_bounds__(256, 1)
void pair_kernel(const float* __restrict__ b2g, float* __restrict__ out)
{
    extern __shared__ char sm[];
    __half*   sW1h = (__half*)(sm + O_W1H);
    __half*   sW2h = (__half*)(sm + O_W2H);
    __half*   sF   = (__half*)(sm + O_F);
    uint32_t* sFu  = (uint32_t*)(sm + O_F);
    float*    sKE  = (float*)(sm + O_KE);
    float*    sAQ  = (float*)(sm + O_AQ);
    float*    sQE  = (float*)(sm + O_QE);
    float*    sB2  = (float*)(sm + O_B2);

    const int tid = threadIdx.x;
    const int b   = blockIdx.z;
    const int k0  = blockIdx.x * 128;
    const int q0  = blockIdx.y * 16;

    // ---------------- phase 0: one-time loads ----------------
    {   // pre-packed fp16 weights: W1h 1664 f4, W2h 1088 f4
        float4* d1 = (float4*)sW1h; const float4* s1 = (const float4*)g_W1h;
        for (int i = tid; i < 1664; i += 256) d1[i] = s1[i];
        float4* d2 = (float4*)sW2h; const float4* s2 = (const float4*)g_W2h;
        for (int i = tid; i < 1088; i += 256) d2[i] = s2[i];
    }
    {   // ke: packed 96-float rows, 128 rows (3072 f4)
        const float4* src = (const float4*)(g_ke + (size_t)(b * NK_ + k0) * 96);
        float4* dst = (float4*)sKE;
        for (int i = tid; i < 3072; i += 256) dst[i] = src[i];
    }
    {   // ki -> F cols 64..95 (uint32 cols 32..47), rows kk and 128+kk
        for (int i = tid; i < 2048; i += 256) {
            const int kk = i >> 4, c = i & 15;
            const uint32_t v = g_kih[(size_t)(b * NK_ + k0 + kk) * 16 + c];
            sFu[kk * 52 + 32 + c]         = v;
            sFu[(128 + kk) * 52 + 32 + c] = v;
        }
    }
    {   // qe: 16 rows = 384 f4 ; Aq: 16 rows = 512 f4
        for (int i = tid; i < 384; i += 256)
            ((float4*)sQE)[i] = *(const float4*)(g_qe + (size_t)(b * NQ_ + q0) * 96 + i * 4);
        for (int i = tid; i < 512; i += 256)
            ((float4*)sAQ)[i] = *(const float4*)(g_Aq + (size_t)(b * NQ_ + q0) * 128 + i * 4);
        if (tid >= 192 && tid < 256) sB2[tid - 192] = b2g[tid - 192];
    }
    __syncthreads();

    // ---------------- warp/lane geometry ----------------
    const int wid = tid >> 5, lane = tid & 31;
    const int grp = lane >> 2, tig = lane & 3;
    const int mb  = wid * 32;                  // warp M-tile: rows mb..mb+31

    const uint32_t sFb  = smem_u32(sF);
    const uint32_t sW1b = smem_u32(sW1h);
    const uint32_t sW2b = smem_u32(sW2h);

    const int arow = lane & 15;
    const int akof = (lane >> 4) * 16;
    const int brow = (lane & 7) + ((lane >> 4) << 3);
    const int bkof = ((lane >> 3) & 1) * 16;

    // ---------------- pass loop: 8 x (2q x 128k) ----------------
    #pragma unroll 1
    for (int pass = 0; pass < 8; pass++) {
        // ---- feats: dot + dist -> F cols 0..63 (fp16), 256 pairs ----
        #pragma unroll
        for (int it = 0; it < 8; it++) {
            const int g  = tid + it * 256;
            const int p  = g >> 3;             // pair 0..255
            const int m  = (g & 7) * 4;
            const int qq = pass * 2 + (p >> 7), kk = p & 127;
            float4 dot = make_float4(0.f, 0.f, 0.f, 0.f);
            float4 d2  = make_float4(0.f, 0.f, 0.f, 0.f);
            #pragma unroll
            for (int c = 0; c < 3; c++) {
                const float4 a  = *(const float4*)&sQE[qq * 96 + c * 32 + m];
                const float4 bb = *(const float4*)&sKE[kk * 96 + c * 32 + m];
                dot.x = fmaf(a.x, bb.x, dot.x);
                dot.y = fmaf(a.y, bb.y, dot.y);
                dot.z = fmaf(a.z, bb.z, dot.z);
                dot.w = fmaf(a.w, bb.w, dot.w);
                float dx = a.x - bb.x; d2.x = fmaf(dx, dx, d2.x);
                float dy = a.y - bb.y; d2.y = fmaf(dy, dy, d2.y);
                float dz = a.z - bb.z; d2.z = fmaf(dz, dz, d2.z);
                float dw = a.w - bb.w; d2.w = fmaf(dw, dw, d2.w);
            }
            *(__half2*)(sF + p * 104 + m)          = __floats2half2_rn(dot.x, dot.y);
            *(__half2*)(sF + p * 104 + m + 2)      = __floats2half2_rn(dot.z, dot.w);
            *(__half2*)(sF + p * 104 + 32 + m)     = __floats2half2_rn(sqrtf(d2.x), sqrtf(d2.y));
            *(__half2*)(sF + p * 104 + 32 + m + 2) = __floats2half2_rn(sqrtf(d2.z), sqrtf(d2.w));
        }
        __syncthreads();

        const int qrow = pass * 2 + (wid >> 2);

        // ---- GEMM1 + epilogue 1 in two N=64 halves (caps register peak) ----
        uint32_t a2[2][8][4];
        #pragma unroll
        for (int half = 0; half < 2; half++) {
            float c1[2][8][4];                 // 64 regs, dies before next half
            #pragma unroll
            for (int mt = 0; mt < 2; mt++)
                #pragma unroll
                for (int nt = 0; nt < 8; nt++)
                    #pragma unroll
                    for (int j = 0; j < 4; j++) c1[mt][nt][j] = 0.f;

            #pragma unroll
            for (int ks = 0; ks < 6; ks++) {
                uint32_t a[2][4];
                ldmx4(a[0], sFb + (mb + arow) * 208 + ks * 32 + akof);
                ldmx4(a[1], sFb + (mb + 16 + arow) * 208 + ks * 32 + akof);
                #pragma unroll
                for (int np = 0; np < 4; np++) {
                    uint32_t bb[4];
                    ldmx4(bb, sW1b + (half * 64 + np * 16 + brow) * 208 + ks * 32 + bkof);
                    #pragma unroll
                    for (int mt = 0; mt < 2; mt++) {
                        mma16816(c1[mt][np * 2 + 0], a[mt], bb[0], bb[1]);
                        mma16816(c1[mt][np * 2 + 1], a[mt], bb[2], bb[3]);
                    }
                }
            }

            // fold this half into a2 k-tiles (global ks = half*4 + kt)
            #pragma unroll
            for (int kt = 0; kt < 4; kt++) {
                #pragma unroll
                for (int hnt = 0; hnt < 2; hnt++) {
                    const int nt = kt * 2 + hnt;
                    const int f  = half * 64 + nt * 8 + tig * 2;
                    const float aq0 = sAQ[qrow * 128 + f];
                    const float aq1 = sAQ[qrow * 128 + f + 1];
                    #pragma unroll
                    for (int mt = 0; mt < 2; mt++) {
                        const float v0 = silu_f(c1[mt][nt][0] + aq0);
                        const float v1 = silu_f(c1[mt][nt][1] + aq1);
                        const float v2 = silu_f(c1[mt][nt][2] + aq0);
                        const float v3 = silu_f(c1[mt][nt][3] + aq1);
                        a2[mt][half * 4 + kt][hnt * 2 + 0] = pack2(v0, v1);
                        a2[mt][half * 4 + kt][hnt * 2 + 1] = pack2(v2, v3);
                    }
                }
            }
        }

        // ---- GEMM2: D2[32x64] = H[32x128] @ W2 (A from registers) ----
        float c2[2][8][4];
        #pragma unroll
        for (int mt = 0; mt < 2; mt++)
            #pragma unroll
            for (int nt = 0; nt < 8; nt++)
                #pragma unroll
                for (int j = 0; j < 4; j++) c2[mt][nt][j] = 0.f;

        #pragma unroll
        for (int ks = 0; ks < 8; ks++) {
            #pragma unroll
            for (int np = 0; np < 4; np++) {
                uint32_t bb[4];
                ldmx4(bb, sW2b + (np * 16 + brow) * 272 + ks * 32 + bkof);
                #pragma unroll
                for (int mt = 0; mt < 2; mt++) {
                    mma16816(c2[mt][np * 2 + 0], a2[mt][ks], bb[0], bb[1]);
                    mma16816(c2[mt][np * 2 + 1], a2[mt][ks], bb[2], bb[3]);
                }
            }
        }

        // ---- epilogue 2: +b2, store ----
        {
            const int q = q0 + pass * 2 + (wid >> 2);
            #pragma unroll
            for (int mt = 0; mt < 2; mt++) {
                #pragma unroll
                for (int h = 0; h < 2; h++) {
                    const int kk = (wid & 3) * 32 + mt * 16 + grp + h * 8;
                    const size_t base = ((size_t)(b * NQ_ + q) * NK_ + k0 + kk) * 64;
                    #pragma unroll
                    for (int nt = 0; nt < 8; nt++) {
                        const int f = nt * 8 + tig * 2;
                        float2 v;
                        v.x = c2[mt][nt][h * 2 + 0] + sB2[f];
                        v.y = c2[mt][nt][h * 2 + 1] + sB2[f + 1];
                        *(float2*)&out[base + f] = v;
                    }
                }
            }
        }
        __syncthreads();   // F reads done CTA-wide before next pass overwrites
    }
}

// =====================================================================
extern "C" void kernel_launch(void* const* d_in, const int* in_sizes, int n_in,
                              void* d_out, int out_size)
{
    (void)in_sizes; (void)n_in; (void)out_size;
    const float* q_equi = (const float*)d_in[0];
    const float* q_inv  = (const float*)d_in[1];
    const float* k_equi = (const float*)d_in[2];
    const float* k_inv  = (const float*)d_in[3];
    const float* Wqi = (const float*)d_in[4];  const float* bqi = (const float*)d_in[5];
    const float* Wki = (const float*)d_in[6];  const float* bki = (const float*)d_in[7];
    const float* Wqe = (const float*)d_in[8];  const float* bqe = (const float*)d_in[9];
    const float* Wke = (const float*)d_in[10]; const float* bke = (const float*)d_in[11];
    const float* W1  = (const float*)d_in[12]; const float* b1  = (const float*)d_in[13];
    const float* W2  = (const float*)d_in[14]; const float* b2  = (const float*)d_in[15];
    float* out = (float*)d_out;

    cudaFuncSetAttribute(pair_kernel, cudaFuncAttributeMaxDynamicSharedMemorySize, SMEM_TOTAL);

    proj_kernel<<<dim3(B_ * NQ_, 3), 128>>>(q_equi, q_inv, k_equi, k_inv,
                                            Wqi, bqi, Wki, bki,
                                            Wqe, bqe, Wke, bke, W1, b1, W2);
    pair_kernel<<<dim3(NK_ / 128, NQ_ / 16, B_), 256, SMEM_TOTAL>>>(b2, out);
}

// round 10
// speedup vs baseline: 1.1770x; 1.1762x over previous
#include <cuda_runtime.h>
#include <cuda_fp16.h>
#include <stdint.h>
#include <stddef.h>

// ---------------- problem constants ----------------
#define B_    2
#define NQ_   768
#define NK_   768

// ---------------- static scratch ----------------
__device__ float    g_qe [B_*NQ_*96];       // [b,q, c*32+m]
__device__ float    g_keT[B_*96*NK_];       // [b][ch=c*32+m][k]  transposed
__device__ float    g_Aq [B_*NQ_*128];      // b1 + qi @ W1[0:32]
__device__ uint32_t g_kiT[B_*16*NK_];       // [b][cp][k]: half2(ki[2cp],ki[2cp+1])
__device__ uint32_t g_W1h[128*52];          // [n][kq] B-tile for A=[dot|dist|ki] (K=96)
__device__ uint32_t g_W2h[64*68];           // [n][kq] half2{W2[2kq][n], W2[2kq+1][n]}

// ---------------- helpers ----------------
__device__ __forceinline__ uint32_t smem_u32(const void* p){
    uint32_t a;
    asm("{ .reg .u64 t; cvta.to.shared.u64 t, %1; cvt.u32.u64 %0, t; }" : "=r"(a) : "l"(p));
    return a;
}
__device__ __forceinline__ float tanh_ap(float x){
    float y; asm("tanh.approx.f32 %0, %1;" : "=f"(y) : "f"(x)); return y;
}
__device__ __forceinline__ float silu_f(float v){
    const float hv = 0.5f * v;
    return fmaf(hv, tanh_ap(hv), hv);          // v * sigmoid(v)
}
__device__ __forceinline__ uint32_t pack2(float a, float b){
    __half2 h = __floats2half2_rn(a, b);
    return *(const uint32_t*)&h;
}
__device__ __forceinline__ void ldmx4(uint32_t* r, uint32_t addr){
    asm volatile("ldmatrix.sync.aligned.m8n8.x4.shared.b16 {%0,%1,%2,%3}, [%4];"
        : "=r"(r[0]), "=r"(r[1]), "=r"(r[2]), "=r"(r[3]) : "r"(addr));
}
__device__ __forceinline__ void mma16816(float* d, const uint32_t* a, uint32_t b0, uint32_t b1){
    asm volatile(
        "mma.sync.aligned.m16n8k16.row.col.f32.f16.f16.f32 "
        "{%0,%1,%2,%3}, {%4,%5,%6,%7}, {%8,%9}, {%0,%1,%2,%3};"
        : "+f"(d[0]), "+f"(d[1]), "+f"(d[2]), "+f"(d[3])
        : "r"(a[0]), "r"(a[1]), "r"(a[2]), "r"(a[3]), "r"(b0), "r"(b1));
}

// ---------------- smem layout (bytes) ----------------
#define O_W1H 0                 // [128 n][104 k] fp16, stride 208B   = 26624
#define O_W2H 26624             // [ 64 n][136 k] fp16, stride 272B   = 17408
#define O_KET 44032             // [96 ch][68 kk] fp32 (stride 68)    = 26112
#define O_KIT 70144             // [16 cp][72 kk] u32  (stride 72)    = 4608
#define O_AQ  74752             // [16][128] fp32                     = 8192
#define O_QE  82944             // [16][96] fp32                      = 6144
#define O_B2  89088             // [64] fp32                          = 256
#define SMEM_TOTAL 89344

// =====================================================================
// Kernel P: per-row projections (side 0/1) + weight prep (side 2).
// =====================================================================
__global__ __launch_bounds__(128)
void proj_kernel(const float* __restrict__ q_equi, const float* __restrict__ q_inv,
                 const float* __restrict__ k_equi, const float* __restrict__ k_inv,
                 const float* __restrict__ Wqi, const float* __restrict__ bqi,
                 const float* __restrict__ Wki, const float* __restrict__ bki,
                 const float* __restrict__ Wqe, const float* __restrict__ bqe,
                 const float* __restrict__ Wke, const float* __restrict__ bke,
                 const float* __restrict__ W1,  const float* __restrict__ b1,
                 const float* __restrict__ W2)
{
    const int side = blockIdx.y;
    const int r    = blockIdx.x;           // b*768 + n  (sides 0/1)
    const int tid  = threadIdx.x;

    if (side == 2) {
        const int idx = r * 128 + tid;
        if (idx < 128*52) {
            const int n = idx / 52, kq = idx % 52;
            float a = 0.f, b = 0.f;
            if (kq < 48) {
                const int a0 = 2*kq, a1 = 2*kq + 1;
                const int r0 = (a0 < 64) ? (64 + a0) : (a0 - 32);
                const int r1 = (a1 < 64) ? (64 + a1) : (a1 - 32);
                a = W1[(size_t)r0 * 128 + n];
                b = W1[(size_t)r1 * 128 + n];
            }
            g_W1h[n*52 + kq] = pack2(a, b);
        } else if (idx < 128*52 + 64*68) {
            const int j = idx - 128*52;
            const int n = j / 68, kq = j % 68;
            float a = 0.f, b = 0.f;
            if (kq < 64) {
                a = W2[(size_t)(2*kq    ) * 64 + n];
                b = W2[(size_t)(2*kq + 1) * 64 + n];
            }
            g_W2h[n*68 + kq] = pack2(a, b);
        }
        return;
    }

    const float* xe = side ? k_equi : q_equi;
    const float* xi = side ? k_inv  : q_inv;
    const float* We = side ? Wke : Wqe;
    const float* be = side ? bke : bqe;
    const float* Wi = side ? Wki : Wqi;
    const float* bi = side ? bki : bqi;

    __shared__ float sxe[768];
    __shared__ float sxi[256];
    __shared__ float spi[32];

    for (int i = tid; i < 768; i += 128) sxe[i] = xe[(size_t)r * 768 + i];
    for (int i = tid; i < 256; i += 128) sxi[i] = xi[(size_t)r * 256 + i];
    __syncthreads();

    const int bb = r >= 768 ? 1 : 0;
    const int n  = r - bb * 768;

    if (tid < 96) {
        const int c = tid >> 5, m = tid & 31;
        float acc = be[m];
        #pragma unroll 4
        for (int d = 0; d < 256; d++)
            acc = fmaf(sxe[c * 256 + d], We[d * 32 + m], acc);
        if (side) g_keT[((size_t)bb * 96 + tid) * NK_ + n] = acc;   // transposed
        else      g_qe [(size_t)r * 96 + tid] = acc;
    } else {
        const int m = tid - 96;
        float acc = bi[m];
        #pragma unroll 4
        for (int d = 0; d < 256; d++)
            acc = fmaf(sxi[d], Wi[d * 32 + m], acc);
        spi[m] = acc;
    }
    __syncthreads();

    if (side) {
        if (tid < 16)
            g_kiT[((size_t)bb * 16 + tid) * NK_ + n] = pack2(spi[2*tid], spi[2*tid + 1]);
    } else {
        float acc = b1[tid];
        #pragma unroll
        for (int m = 0; m < 32; m++)
            acc = fmaf(spi[m], W1[m * 128 + tid], acc);
        g_Aq[(size_t)r * 128 + tid] = acc;
    }
}

// =====================================================================
// Kernel B: pairwise kernel, fragment-direct feats.
//   CTA = 16 q-rows x 64 k-rows; 8 passes of (2q x 64k, M=128).
//   All smem read-only after phase 0 -> NO barriers in the pass loop.
// =====================================================================
__global__ __launch_bounds__(256, 2)
void pair_kernel(const float* __restrict__ b2g, float* __restrict__ out)
{
    extern __shared__ char sm[];
    __half*   sW1h = (__half*)(sm + O_W1H);
    __half*   sW2h = (__half*)(sm + O_W2H);
    float*    sKET = (float*)(sm + O_KET);
    uint32_t* sKIT = (uint32_t*)(sm + O_KIT);
    float*    sAQ  = (float*)(sm + O_AQ);
    float*    sQE  = (float*)(sm + O_QE);
    float*    sB2  = (float*)(sm + O_B2);

    const int tid = threadIdx.x;
    const int b   = blockIdx.z;
    const int k0  = blockIdx.x * 64;
    const int q0  = blockIdx.y * 16;

    // ---------------- phase 0: one-time loads ----------------
    {   // pre-packed fp16 weights: W1h 1664 f4, W2h 1088 f4
        float4* d1 = (float4*)sW1h; const float4* s1 = (const float4*)g_W1h;
        for (int i = tid; i < 1664; i += 256) d1[i] = s1[i];
        float4* d2 = (float4*)sW2h; const float4* s2 = (const float4*)g_W2h;
        for (int i = tid; i < 1088; i += 256) d2[i] = s2[i];
    }
    {   // keT: 96 rows x 16 f4, smem stride 68 floats
        for (int i = tid; i < 1536; i += 256) {
            const int row = i >> 4, c4 = i & 15;
            *(float4*)(sKET + row * 68 + c4 * 4) =
                *(const float4*)(g_keT + ((size_t)b * 96 + row) * NK_ + k0 + c4 * 4);
        }
    }
    {   // kiT: 16 rows x 16 uint4, smem stride 72 u32
        for (int i = tid; i < 256; i += 256) {
            const int row = i >> 4, c4 = i & 15;
            *(uint4*)(sKIT + row * 72 + c4 * 4) =
                *(const uint4*)(g_kiT + ((size_t)b * 16 + row) * NK_ + k0 + c4 * 4);
        }
    }
    {   // qe: 16 rows = 384 f4 ; Aq: 16 rows = 512 f4
        for (int i = tid; i < 384; i += 256)
            ((float4*)sQE)[i] = *(const float4*)(g_qe + (size_t)(b * NQ_ + q0) * 96 + i * 4);
        for (int i = tid; i < 512; i += 256)
            ((float4*)sAQ)[i] = *(const float4*)(g_Aq + (size_t)(b * NQ_ + q0) * 128 + i * 4);
        if (tid >= 192 && tid < 256) sB2[tid - 192] = b2g[tid - 192];
    }
    __syncthreads();   // the ONLY barrier

    // ---------------- warp/lane geometry ----------------
    const int wid = tid >> 5, lane = tid & 31;
    const int grp = lane >> 2, tig = lane & 3;
    const int kbase = (wid & 3) * 16;
    const int kk1 = kbase + grp, kk2 = kbase + grp + 8;
    const int qq  = wid >> 2;

    const uint32_t sW1b = smem_u32(sW1h);
    const uint32_t sW2b = smem_u32(sW2h);

    const int brow = (lane & 7) + ((lane >> 4) << 3);
    const int bkof = ((lane >> 3) & 1) * 16;

    // ---------------- pass loop: 8 x (2q x 64k), no barriers ----------------
    #pragma unroll 1
    for (int pass = 0; pass < 8; pass++) {
        const int qrow = pass * 2 + qq;

        // ---- feats directly into GEMM1 A-fragments ----
        uint32_t aDot[2][4], aDist[2][4], aKi[2][4];
        {
            float dotv[2][8], d2v[2][8];
            #pragma unroll
            for (int j = 0; j < 8; j++) {
                const int m = 2 * tig + (j & 1) + (j >> 1) * 8;
                float dv0 = 0.f, dv1 = 0.f, s0 = 0.f, s1 = 0.f;
                #pragma unroll
                for (int c = 0; c < 3; c++) {
                    const int ch = c * 32 + m;
                    const float qv = sQE[qrow * 96 + ch];
                    const float k1 = sKET[ch * 68 + kk1];
                    const float k2 = sKET[ch * 68 + kk2];
                    dv0 = fmaf(qv, k1, dv0);
                    dv1 = fmaf(qv, k2, dv1);
                    const float e1 = qv - k1; s0 = fmaf(e1, e1, s0);
                    const float e2 = qv - k2; s1 = fmaf(e2, e2, s1);
                }
                dotv[0][j] = dv0; dotv[1][j] = dv1;
                d2v[0][j]  = s0;  d2v[1][j]  = s1;
            }
            #pragma unroll
            for (int ks = 0; ks < 2; ks++) {
                aDot[ks][0] = pack2(dotv[0][ks*4+0], dotv[0][ks*4+1]);
                aDot[ks][1] = pack2(dotv[1][ks*4+0], dotv[1][ks*4+1]);
                aDot[ks][2] = pack2(dotv[0][ks*4+2], dotv[0][ks*4+3]);
                aDot[ks][3] = pack2(dotv[1][ks*4+2], dotv[1][ks*4+3]);
                aDist[ks][0] = pack2(sqrtf(d2v[0][ks*4+0]), sqrtf(d2v[0][ks*4+1]));
                aDist[ks][1] = pack2(sqrtf(d2v[1][ks*4+0]), sqrtf(d2v[1][ks*4+1]));
                aDist[ks][2] = pack2(sqrtf(d2v[0][ks*4+2]), sqrtf(d2v[0][ks*4+3]));
                aDist[ks][3] = pack2(sqrtf(d2v[1][ks*4+2]), sqrtf(d2v[1][ks*4+3]));
            }
            #pragma unroll
            for (int ks = 0; ks < 2; ks++) {
                const int cp = tig + ks * 8;
                aKi[ks][0] = sKIT[cp * 72 + kk1];
                aKi[ks][1] = sKIT[cp * 72 + kk2];
                aKi[ks][2] = sKIT[(cp + 4) * 72 + kk1];
                aKi[ks][3] = sKIT[(cp + 4) * 72 + kk2];
            }
        }

        // ---- GEMM1: D1[16x128] = A(K=96, from regs) @ W1h ----
        float c1[16][4];
        #pragma unroll
        for (int nt = 0; nt < 16; nt++)
            #pragma unroll
            for (int j = 0; j < 4; j++) c1[nt][j] = 0.f;

        #pragma unroll
        for (int ks = 0; ks < 6; ks++) {
            const uint32_t* A = (ks < 2) ? aDot[ks] : (ks < 4) ? aDist[ks-2] : aKi[ks-4];
            #pragma unroll
            for (int np = 0; np < 8; np++) {
                uint32_t bb[4];
                ldmx4(bb, sW1b + (np * 16 + brow) * 208 + ks * 32 + bkof);
                mma16816(c1[np * 2 + 0], A, bb[0], bb[1]);
                mma16816(c1[np * 2 + 1], A, bb[2], bb[3]);
            }
        }

        // ---- epilogue 1 (regs): +Aq, silu -> GEMM2 A-fragments ----
        uint32_t a2[8][4];
        #pragma unroll
        for (int kt = 0; kt < 8; kt++) {
            #pragma unroll
            for (int hnt = 0; hnt < 2; hnt++) {
                const int nt = kt * 2 + hnt;
                const int f  = nt * 8 + tig * 2;
                const float aq0 = sAQ[qrow * 128 + f];
                const float aq1 = sAQ[qrow * 128 + f + 1];
                const float v0 = silu_f(c1[nt][0] + aq0);
                const float v1 = silu_f(c1[nt][1] + aq1);
                const float v2 = silu_f(c1[nt][2] + aq0);
                const float v3 = silu_f(c1[nt][3] + aq1);
                a2[kt][hnt * 2 + 0] = pack2(v0, v1);
                a2[kt][hnt * 2 + 1] = pack2(v2, v3);
            }
        }

        // ---- GEMM2: D2[16x64] = H[16x128] @ W2 (A from registers) ----
        float c2[8][4];
        #pragma unroll
        for (int nt = 0; nt < 8; nt++)
            #pragma unroll
            for (int j = 0; j < 4; j++) c2[nt][j] = 0.f;

        #pragma unroll
        for (int ks = 0; ks < 8; ks++) {
            #pragma unroll
            for (int np = 0; np < 4; np++) {
                uint32_t bb[4];
                ldmx4(bb, sW2b + (np * 16 + brow) * 272 + ks * 32 + bkof);
                mma16816(c2[np * 2 + 0], a2[ks], bb[0], bb[1]);
                mma16816(c2[np * 2 + 1], a2[ks], bb[2], bb[3]);
            }
        }

        // ---- epilogue 2: +b2, store ----
        {
            const int q = q0 + qrow;
            #pragma unroll
            for (int h = 0; h < 2; h++) {
                const int kk = kbase + grp + h * 8;
                const size_t base = ((size_t)(b * NQ_ + q) * NK_ + k0 + kk) * 64;
                #pragma unroll
                for (int nt = 0; nt < 8; nt++) {
                    const int f = nt * 8 + tig * 2;
                    float2 v;
                    v.x = c2[nt][h * 2 + 0] + sB2[f];
                    v.y = c2[nt][h * 2 + 1] + sB2[f + 1];
                    *(float2*)&out[base + f] = v;
                }
            }
        }
    }
}

// =====================================================================
extern "C" void kernel_launch(void* const* d_in, const int* in_sizes, int n_in,
                              void* d_out, int out_size)
{
    (void)in_sizes; (void)n_in; (void)out_size;
    const float* q_equi = (const float*)d_in[0];
    const float* q_inv  = (const float*)d_in[1];
    const float* k_equi = (const float*)d_in[2];
    const float* k_inv  = (const float*)d_in[3];
    const float* Wqi = (const float*)d_in[4];  const float* bqi = (const float*)d_in[5];
    const float* Wki = (const float*)d_in[6];  const float* bki = (const float*)d_in[7];
    const float* Wqe = (const float*)d_in[8];  const float* bqe = (const float*)d_in[9];
    const float* Wke = (const float*)d_in[10]; const float* bke = (const float*)d_in[11];
    const float* W1  = (const float*)d_in[12]; const float* b1  = (const float*)d_in[13];
    const float* W2  = (const float*)d_in[14]; const float* b2  = (const float*)d_in[15];
    float* out = (float*)d_out;

    cudaFuncSetAttribute(pair_kernel, cudaFuncAttributeMaxDynamicSharedMemorySize, SMEM_TOTAL);

    proj_kernel<<<dim3(B_ * NQ_, 3), 128>>>(q_equi, q_inv, k_equi, k_inv,
                                            Wqi, bqi, Wki, bki,
                                            Wqe, bqe, Wke, bke, W1, b1, W2);
    pair_kernel<<<dim3(NK_ / 64, NQ_ / 16, B_), 256, SMEM_TOTAL>>>(b2, out);
}

// round 11
// speedup vs baseline: 1.2010x; 1.0204x over previous
#include <cuda_runtime.h>
#include <cuda_fp16.h>
#include <stdint.h>
#include <stddef.h>

// ---------------- problem constants ----------------
#define B_    2
#define NQ_   768
#define NK_   768

// ---------------- static scratch ----------------
__device__ float    g_qe [B_*NQ_*96];       // [b,q, c*32+m]
__device__ float    g_keT[B_*96*NK_];       // [b][ch=c*32+m][k]  transposed
__device__ float    g_Aq [B_*NQ_*128];      // b1 + qi @ W1[0:32]
__device__ uint32_t g_kiT[B_*16*NK_];       // [b][cp][k]: half2(ki[2cp],ki[2cp+1])
__device__ uint32_t g_W1h[128*52];          // [n][kq] B-tile for A=[dot|dist|ki] (K=96)
__device__ uint32_t g_W2h[64*68];           // [n][kq] half2{W2[2kq][n], W2[2kq+1][n]}

// ---------------- helpers ----------------
__device__ __forceinline__ uint32_t smem_u32(const void* p){
    uint32_t a;
    asm("{ .reg .u64 t; cvta.to.shared.u64 t, %1; cvt.u32.u64 %0, t; }" : "=r"(a) : "l"(p));
    return a;
}
__device__ __forceinline__ float tanh_ap(float x){
    float y; asm("tanh.approx.f32 %0, %1;" : "=f"(y) : "f"(x)); return y;
}
__device__ __forceinline__ float silu_f(float v){
    const float hv = 0.5f * v;
    return fmaf(hv, tanh_ap(hv), hv);          // v * sigmoid(v)
}
__device__ __forceinline__ uint32_t pack2(float a, float b){
    __half2 h = __floats2half2_rn(a, b);
    return *(const uint32_t*)&h;
}
__device__ __forceinline__ void ldmx4(uint32_t* r, uint32_t addr){
    asm volatile("ldmatrix.sync.aligned.m8n8.x4.shared.b16 {%0,%1,%2,%3}, [%4];"
        : "=r"(r[0]), "=r"(r[1]), "=r"(r[2]), "=r"(r[3]) : "r"(addr));
}
__device__ __forceinline__ void mma16816(float* d, const uint32_t* a, uint32_t b0, uint32_t b1){
    asm volatile(
        "mma.sync.aligned.m16n8k16.row.col.f32.f16.f16.f32 "
        "{%0,%1,%2,%3}, {%4,%5,%6,%7}, {%8,%9}, {%0,%1,%2,%3};"
        : "+f"(d[0]), "+f"(d[1]), "+f"(d[2]), "+f"(d[3])
        : "r"(a[0]), "r"(a[1]), "r"(a[2]), "r"(a[3]), "r"(b0), "r"(b1));
}

// ---------------- pair-kernel smem layout (bytes) ----------------
#define O_W1H 0                 // [128 n][104 k] fp16, stride 208B   = 26624
#define O_W2H 26624             // [ 64 n][136 k] fp16, stride 272B   = 17408
#define O_KET 44032             // [96 ch][68 kk] fp32 (stride 68)    = 26112
#define O_KIT 70144             // [16 cp][72 kk] u32  (stride 72)    = 4608
#define O_AQ  74752             // [16][128] fp32                     = 8192
#define O_QE  82944             // [16][96] fp32                      = 6144
#define O_B2  89088             // [64] fp32                          = 256
#define SMEM_TOTAL 89344

// ---------------- proj-kernel smem layout (floats) ----------------
#define P_WE   0                // [256*32]                           = 8192 f
#define P_WI   8192             // [256*32]                           = 8192 f
#define P_W1S  16384            // [32*128] (side 0 only)             = 4096 f
#define P_XE   20480            // [2][768]                           = 1536 f
#define P_XI   22016            // [2][256]                           =  512 f
#define P_PI   22528            // [2][32]                            =   64 f
#define P_BE   22592            // [32]
#define P_BI   22624            // [32]
#define P_B1   22656            // [128]
#define PROJ_FLOATS 22784
#define PROJ_SMEM (PROJ_FLOATS * 4)
#define ROWS_PER_BLK 16

// =====================================================================
// Kernel P: projections (sides 0/1, 16 rows/block, weights in smem)
//           + weight prep (side 2).  grid (96, 3) x 256.
// =====================================================================
__global__ __launch_bounds__(256)
void proj_kernel(const float* __restrict__ q_equi, const float* __restrict__ q_inv,
                 const float* __restrict__ k_equi, const float* __restrict__ k_inv,
                 const float* __restrict__ Wqi, const float* __restrict__ bqi,
                 const float* __restrict__ Wki, const float* __restrict__ bki,
                 const float* __restrict__ Wqe, const float* __restrict__ bqe,
                 const float* __restrict__ Wke, const float* __restrict__ bke,
                 const float* __restrict__ W1,  const float* __restrict__ b1,
                 const float* __restrict__ W2)
{
    const int side = blockIdx.y;
    const int tid  = threadIdx.x;

    if (side == 2) {
        // -------- weight prep: W1h (K=96 A-order [dot|dist|ki]) + W2h --------
        const int idx = blockIdx.x * 256 + tid;
        if (idx < 128*52) {
            const int n = idx / 52, kq = idx % 52;
            float a = 0.f, b = 0.f;
            if (kq < 48) {
                const int a0 = 2*kq, a1 = 2*kq + 1;
                const int r0 = (a0 < 64) ? (64 + a0) : (a0 - 32);
                const int r1 = (a1 < 64) ? (64 + a1) : (a1 - 32);
                a = W1[(size_t)r0 * 128 + n];
                b = W1[(size_t)r1 * 128 + n];
            }
            g_W1h[n*52 + kq] = pack2(a, b);
        } else if (idx < 128*52 + 64*68) {
            const int j = idx - 128*52;
            const int n = j / 68, kq = j % 68;
            float a = 0.f, b = 0.f;
            if (kq < 64) {
                a = W2[(size_t)(2*kq    ) * 64 + n];
                b = W2[(size_t)(2*kq + 1) * 64 + n];
            }
            g_W2h[n*68 + kq] = pack2(a, b);
        }
        return;
    }

    extern __shared__ float ps[];
    float* sWe = ps + P_WE;
    float* sWi = ps + P_WI;
    float* sW1s = ps + P_W1S;
    float* sXE = ps + P_XE;
    float* sXI = ps + P_XI;
    float* sPI = ps + P_PI;
    float* sBE = ps + P_BE;
    float* sBI = ps + P_BI;
    float* sB1 = ps + P_B1;

    const float* xe = side ? k_equi : q_equi;
    const float* xi = side ? k_inv  : q_inv;
    const float* We = side ? Wke : Wqe;
    const float* be = side ? bke : bqe;
    const float* Wi = side ? Wki : Wqi;
    const float* bi = side ? bki : bqi;

    // ---- load weights to smem once per block ----
    {
        float4* d = (float4*)sWe; const float4* s = (const float4*)We;
        for (int i = tid; i < 2048; i += 256) d[i] = s[i];
        d = (float4*)sWi; s = (const float4*)Wi;
        for (int i = tid; i < 2048; i += 256) d[i] = s[i];
        if (!side) {
            d = (float4*)sW1s; s = (const float4*)W1;      // W1 rows 0..31
            for (int i = tid; i < 1024; i += 256) d[i] = s[i];
            for (int i = tid; i < 128; i += 256) sB1[i] = b1[i];
        }
        if (tid < 32)       sBE[tid] = be[tid];
        else if (tid < 64)  sBI[tid - 32] = bi[tid - 32];
    }
    __syncthreads();

    const int half = tid >> 7;           // two rows in flight
    const int ltid = tid & 127;
    const int rbase = blockIdx.x * ROWS_PER_BLK;

    #pragma unroll 1
    for (int rp = 0; rp < ROWS_PER_BLK / 2; rp++) {
        const int r  = rbase + rp * 2 + half;       // global row: b*768 + n
        const int bb = r >= 768 ? 1 : 0;
        const int n  = r - bb * 768;

        // ---- stream this row's inputs ----
        {
            const float* src = xe + (size_t)r * 768;
            #pragma unroll
            for (int i = 0; i < 6; i++) sXE[half * 768 + ltid + i * 128] = src[ltid + i * 128];
            const float* si = xi + (size_t)r * 256;
            #pragma unroll
            for (int i = 0; i < 2; i++) sXI[half * 256 + ltid + i * 128] = si[ltid + i * 128];
        }
        __syncthreads();

        // ---- projections ----
        if (ltid < 96) {
            const int c = ltid >> 5, m = ltid & 31;
            float acc = sBE[m];
            #pragma unroll 4
            for (int d = 0; d < 256; d++)
                acc = fmaf(sXE[half * 768 + c * 256 + d], sWe[d * 32 + m], acc);
            if (side) g_keT[((size_t)bb * 96 + ltid) * NK_ + n] = acc;   // transposed
            else      g_qe [(size_t)r * 96 + ltid] = acc;
        } else {
            const int m = ltid - 96;
            float acc = sBI[m];
            #pragma unroll 4
            for (int d = 0; d < 256; d++)
                acc = fmaf(sXI[half * 256 + d], sWi[d * 32 + m], acc);
            sPI[half * 32 + m] = acc;
        }
        __syncthreads();

        if (side) {
            if (ltid < 16)
                g_kiT[((size_t)bb * 16 + ltid) * NK_ + n] =
                    pack2(sPI[half * 32 + 2*ltid], sPI[half * 32 + 2*ltid + 1]);
        } else {
            float acc = sB1[ltid];
            #pragma unroll
            for (int m = 0; m < 32; m++)
                acc = fmaf(sPI[half * 32 + m], sW1s[m * 128 + ltid], acc);
            g_Aq[(size_t)r * 128 + ltid] = acc;
        }
        __syncthreads();   // sXE/sXI/sPI reuse next iteration
    }
}

// =====================================================================
// Kernel B: pairwise kernel, fragment-direct feats (unchanged from R10).
//   CTA = 16 q-rows x 64 k-rows; 8 passes of (2q x 64k, M=128).
// =====================================================================
__global__ __launch_bounds__(256, 2)
void pair_kernel(const float* __restrict__ b2g, float* __restrict__ out)
{
    extern __shared__ char sm[];
    __half*   sW1h = (__half*)(sm + O_W1H);
    __half*   sW2h = (__half*)(sm + O_W2H);
    float*    sKET = (float*)(sm + O_KET);
    uint32_t* sKIT = (uint32_t*)(sm + O_KIT);
    float*    sAQ  = (float*)(sm + O_AQ);
    float*    sQE  = (float*)(sm + O_QE);
    float*    sB2  = (float*)(sm + O_B2);

    const int tid = threadIdx.x;
    const int b   = blockIdx.z;
    const int k0  = blockIdx.x * 64;
    const int q0  = blockIdx.y * 16;

    // ---------------- phase 0: one-time loads ----------------
    {   // pre-packed fp16 weights: W1h 1664 f4, W2h 1088 f4
        float4* d1 = (float4*)sW1h; const float4* s1 = (const float4*)g_W1h;
        for (int i = tid; i < 1664; i += 256) d1[i] = s1[i];
        float4* d2 = (float4*)sW2h; const float4* s2 = (const float4*)g_W2h;
        for (int i = tid; i < 1088; i += 256) d2[i] = s2[i];
    }
    {   // keT: 96 rows x 16 f4, smem stride 68 floats
        for (int i = tid; i < 1536; i += 256) {
            const int row = i >> 4, c4 = i & 15;
            *(float4*)(sKET + row * 68 + c4 * 4) =
                *(const float4*)(g_keT + ((size_t)b * 96 + row) * NK_ + k0 + c4 * 4);
        }
    }
    {   // kiT: 16 rows x 16 uint4, smem stride 72 u32
        for (int i = tid; i < 256; i += 256) {
            const int row = i >> 4, c4 = i & 15;
            *(uint4*)(sKIT + row * 72 + c4 * 4) =
                *(const uint4*)(g_kiT + ((size_t)b * 16 + row) * NK_ + k0 + c4 * 4);
        }
    }
    {   // qe: 16 rows = 384 f4 ; Aq: 16 rows = 512 f4
        for (int i = tid; i < 384; i += 256)
            ((float4*)sQE)[i] = *(const float4*)(g_qe + (size_t)(b * NQ_ + q0) * 96 + i * 4);
        for (int i = tid; i < 512; i += 256)
            ((float4*)sAQ)[i] = *(const float4*)(g_Aq + (size_t)(b * NQ_ + q0) * 128 + i * 4);
        if (tid >= 192 && tid < 256) sB2[tid - 192] = b2g[tid - 192];
    }
    __syncthreads();   // the ONLY barrier

    // ---------------- warp/lane geometry ----------------
    const int wid = tid >> 5, lane = tid & 31;
    const int grp = lane >> 2, tig = lane & 3;
    const int kbase = (wid & 3) * 16;
    const int kk1 = kbase + grp, kk2 = kbase + grp + 8;
    const int qq  = wid >> 2;

    const uint32_t sW1b = smem_u32(sW1h);
    const uint32_t sW2b = smem_u32(sW2h);

    const int brow = (lane & 7) + ((lane >> 4) << 3);
    const int bkof = ((lane >> 3) & 1) * 16;

    // ---------------- pass loop: 8 x (2q x 64k), no barriers ----------------
    #pragma unroll 1
    for (int pass = 0; pass < 8; pass++) {
        const int qrow = pass * 2 + qq;

        // ---- feats directly into GEMM1 A-fragments ----
        uint32_t aDot[2][4], aDist[2][4], aKi[2][4];
        {
            float dotv[2][8], d2v[2][8];
            #pragma unroll
            for (int j = 0; j < 8; j++) {
                const int m = 2 * tig + (j & 1) + (j >> 1) * 8;
                float dv0 = 0.f, dv1 = 0.f, s0 = 0.f, s1 = 0.f;
                #pragma unroll
                for (int c = 0; c < 3; c++) {
                    const int ch = c * 32 + m;
                    const float qv = sQE[qrow * 96 + ch];
                    const float k1 = sKET[ch * 68 + kk1];
                    const float k2 = sKET[ch * 68 + kk2];
                    dv0 = fmaf(qv, k1, dv0);
                    dv1 = fmaf(qv, k2, dv1);
                    const float e1 = qv - k1; s0 = fmaf(e1, e1, s0);
                    const float e2 = qv - k2; s1 = fmaf(e2, e2, s1);
                }
                dotv[0][j] = dv0; dotv[1][j] = dv1;
                d2v[0][j]  = s0;  d2v[1][j]  = s1;
            }
            #pragma unroll
            for (int ks = 0; ks < 2; ks++) {
                aDot[ks][0] = pack2(dotv[0][ks*4+0], dotv[0][ks*4+1]);
                aDot[ks][1] = pack2(dotv[1][ks*4+0], dotv[1][ks*4+1]);
                aDot[ks][2] = pack2(dotv[0][ks*4+2], dotv[0][ks*4+3]);
                aDot[ks][3] = pack2(dotv[1][ks*4+2], dotv[1][ks*4+3]);
                aDist[ks][0] = pack2(sqrtf(d2v[0][ks*4+0]), sqrtf(d2v[0][ks*4+1]));
                aDist[ks][1] = pack2(sqrtf(d2v[1][ks*4+0]), sqrtf(d2v[1][ks*4+1]));
                aDist[ks][2] = pack2(sqrtf(d2v[0][ks*4+2]), sqrtf(d2v[0][ks*4+3]));
                aDist[ks][3] = pack2(sqrtf(d2v[1][ks*4+2]), sqrtf(d2v[1][ks*4+3]));
            }
            #pragma unroll
            for (int ks = 0; ks < 2; ks++) {
                const int cp = tig + ks * 8;
                aKi[ks][0] = sKIT[cp * 72 + kk1];
                aKi[ks][1] = sKIT[cp * 72 + kk2];
                aKi[ks][2] = sKIT[(cp + 4) * 72 + kk1];
                aKi[ks][3] = sKIT[(cp + 4) * 72 + kk2];
            }
        }

        // ---- GEMM1: D1[16x128] = A(K=96, from regs) @ W1h ----
        float c1[16][4];
        #pragma unroll
        for (int nt = 0; nt < 16; nt++)
            #pragma unroll
            for (int j = 0; j < 4; j++) c1[nt][j] = 0.f;

        #pragma unroll
        for (int ks = 0; ks < 6; ks++) {
            const uint32_t* A = (ks < 2) ? aDot[ks] : (ks < 4) ? aDist[ks-2] : aKi[ks-4];
            #pragma unroll
            for (int np = 0; np < 8; np++) {
                uint32_t bb[4];
                ldmx4(bb, sW1b + (np * 16 + brow) * 208 + ks * 32 + bkof);
                mma16816(c1[np * 2 + 0], A, bb[0], bb[1]);
                mma16816(c1[np * 2 + 1], A, bb[2], bb[3]);
            }
        }

        // ---- epilogue 1 (regs): +Aq, silu -> GEMM2 A-fragments ----
        uint32_t a2[8][4];
        #pragma unroll
        for (int kt = 0; kt < 8; kt++) {
            #pragma unroll
            for (int hnt = 0; hnt < 2; hnt++) {
                const int nt = kt * 2 + hnt;
                const int f  = nt * 8 + tig * 2;
                const float aq0 = sAQ[qrow * 128 + f];
                const float aq1 = sAQ[qrow * 128 + f + 1];
                const float v0 = silu_f(c1[nt][0] + aq0);
                const float v1 = silu_f(c1[nt][1] + aq1);
                const float v2 = silu_f(c1[nt][2] + aq0);
                const float v3 = silu_f(c1[nt][3] + aq1);
                a2[kt][hnt * 2 + 0] = pack2(v0, v1);
                a2[kt][hnt * 2 + 1] = pack2(v2, v3);
            }
        }

        // ---- GEMM2: D2[16x64] = H[16x128] @ W2 (A from registers) ----
        float c2[8][4];
        #pragma unroll
        for (int nt = 0; nt < 8; nt++)
            #pragma unroll
            for (int j = 0; j < 4; j++) c2[nt][j] = 0.f;

        #pragma unroll
        for (int ks = 0; ks < 8; ks++) {
            #pragma unroll
            for (int np = 0; np < 4; np++) {
                uint32_t bb[4];
                ldmx4(bb, sW2b + (np * 16 + brow) * 272 + ks * 32 + bkof);
                mma16816(c2[np * 2 + 0], a2[ks], bb[0], bb[1]);
                mma16816(c2[np * 2 + 1], a2[ks], bb[2], bb[3]);
            }
        }

        // ---- epilogue 2: +b2, store ----
        {
            const int q = q0 + qrow;
            #pragma unroll
            for (int h = 0; h < 2; h++) {
                const int kk = kbase + grp + h * 8;
                const size_t base = ((size_t)(b * NQ_ + q) * NK_ + k0 + kk) * 64;
                #pragma unroll
                for (int nt = 0; nt < 8; nt++) {
                    const int f = nt * 8 + tig * 2;
                    float2 v;
                    v.x = c2[nt][h * 2 + 0] + sB2[f];
                    v.y = c2[nt][h * 2 + 1] + sB2[f + 1];
                    *(float2*)&out[base + f] = v;
                }
            }
        }
    }
}

// =====================================================================
extern "C" void kernel_launch(void* const* d_in, const int* in_sizes, int n_in,
                              void* d_out, int out_size)
{
    (void)in_sizes; (void)n_in; (void)out_size;
    const float* q_equi = (const float*)d_in[0];
    const float* q_inv  = (const float*)d_in[1];
    const float* k_equi = (const float*)d_in[2];
    const float* k_inv  = (const float*)d_in[3];
    const float* Wqi = (const float*)d_in[4];  const float* bqi = (const float*)d_in[5];
    const float* Wki = (const float*)d_in[6];  const float* bki = (const float*)d_in[7];
    const float* Wqe = (const float*)d_in[8];  const float* bqe = (const float*)d_in[9];
    const float* Wke = (const float*)d_in[10]; const float* bke = (const float*)d_in[11];
    const float* W1  = (const float*)d_in[12]; const float* b1  = (const float*)d_in[13];
    const float* W2  = (const float*)d_in[14]; const float* b2  = (const float*)d_in[15];
    float* out = (float*)d_out;

    cudaFuncSetAttribute(proj_kernel, cudaFuncAttributeMaxDynamicSharedMemorySize, PROJ_SMEM);
    cudaFuncSetAttribute(pair_kernel, cudaFuncAttributeMaxDynamicSharedMemorySize, SMEM_TOTAL);

    proj_kernel<<<dim3(96, 3), 256, PROJ_SMEM>>>(q_equi, q_inv, k_equi, k_inv,
                                                 Wqi, bqi, Wki, bki,
                                                 Wqe, bqe, Wke, bke, W1, b1, W2);
    pair_kernel<<<dim3(NK_ / 64, NQ_ / 16, B_), 256, SMEM_TOTAL>>>(b2, out);
}

// round 13
// speedup vs baseline: 1.2485x; 1.0396x over previous
#include <cuda_runtime.h>
#include <cuda_fp16.h>
#include <stdint.h>
#include <stddef.h>

// ---------------- problem constants ----------------
#define B_    2
#define NQ_   768
#define NK_   768

// ---------------- static scratch ----------------
__device__ float    g_qe [B_*NQ_*96];       // [b,q, c*32+m]
__device__ float    g_keT[B_*96*NK_];       // [b][ch=c*32+m][k]  transposed
__device__ float    g_Aq [B_*NQ_*128];      // b1 + qi @ W1[0:32]
__device__ uint32_t g_Bkh[B_*NK_*64];       // [b,k][f2] half2(Bk[2f2],Bk[2f2+1]), Bk = ki@W1[32:64] (128 f)
__device__ uint32_t g_W1h[128*36];          // [n][kq] B-tile for A=[dot|dist] (K=64)
__device__ uint32_t g_W2h[64*68];           // [n][kq] half2{W2[2kq][n], W2[2kq+1][n]}

// ---------------- helpers ----------------
__device__ __forceinline__ uint32_t smem_u32(const void* p){
    uint32_t a;
    asm("{ .reg .u64 t; cvta.to.shared.u64 t, %1; cvt.u32.u64 %0, t; }" : "=r"(a) : "l"(p));
    return a;
}
__device__ __forceinline__ float tanh_ap(float x){
    float y; asm("tanh.approx.f32 %0, %1;" : "=f"(y) : "f"(x)); return y;
}
__device__ __forceinline__ float silu_f(float v){
    const float hv = 0.5f * v;
    return fmaf(hv, tanh_ap(hv), hv);          // v * sigmoid(v)
}
__device__ __forceinline__ uint32_t pack2(float a, float b){
    __half2 h = __floats2half2_rn(a, b);
    return *(const uint32_t*)&h;
}
__device__ __forceinline__ float2 unpack2(uint32_t u){
    return __half22float2(*(__half2*)&u);
}
__device__ __forceinline__ void ldmx4(uint32_t* r, uint32_t addr){
    asm volatile("ldmatrix.sync.aligned.m8n8.x4.shared.b16 {%0,%1,%2,%3}, [%4];"
        : "=r"(r[0]), "=r"(r[1]), "=r"(r[2]), "=r"(r[3]) : "r"(addr));
}
__device__ __forceinline__ void mma16816(float* d, const uint32_t* a, uint32_t b0, uint32_t b1){
    asm volatile(
        "mma.sync.aligned.m16n8k16.row.col.f32.f16.f16.f32 "
        "{%0,%1,%2,%3}, {%4,%5,%6,%7}, {%8,%9}, {%0,%1,%2,%3};"
        : "+f"(d[0]), "+f"(d[1]), "+f"(d[2]), "+f"(d[3])
        : "r"(a[0]), "r"(a[1]), "r"(a[2]), "r"(a[3]), "r"(b0), "r"(b1));
}

// ---------------- pair-kernel smem layout (bytes) ----------------
#define O_W1H 0                 // [128 n][72 k] fp16, stride 144B    = 18432
#define O_W2H 18432             // [ 64 n][136 k] fp16, stride 272B   = 17408
#define O_KET 35840             // [96 ch][68 kk] fp32 (stride 68)    = 26112
#define O_BKH 61952             // [64 kk][68 f2] u32 (stride 68)     = 17408
#define O_AQ  79360             // [16][128] fp32                     = 8192
#define O_QE  87552             // [16][96] fp32                      = 6144
#define O_B2  93696             // [64] fp32                          = 256
#define SMEM_TOTAL 93952

// ---------------- proj-kernel smem layout (floats) ----------------
#define P_WE   0                // [256*32]                           = 8192 f
#define P_WI   8192             // [256*32]                           = 8192 f
#define P_W1S  16384            // [32*128]                           = 4096 f
#define P_XE   20480            // [2][768]                           = 1536 f
#define P_XI   22016            // [2][256]                           =  512 f
#define P_PI   22528            // [2][32]                            =   64 f
#define P_BE   22592            // [32]
#define P_BI   22624            // [32]
#define P_B1   22656            // [128]
#define PROJ_FLOATS 22784
#define PROJ_SMEM (PROJ_FLOATS * 4)
#define ROWS_PER_BLK 16

// =====================================================================
// Kernel P: projections (sides 0/1, 16 rows/block, weights in smem)
//           + weight prep (side 2).  grid (96, 3) x 256.
//   side 0: qe, Aq = b1 + qi@W1[0:32]
//   side 1: keT (transposed), Bkh = fp16-packed ki@W1[32:64]
// =====================================================================
__global__ __launch_bounds__(256)
void proj_kernel(const float* __restrict__ q_equi, const float* __restrict__ q_inv,
                 const float* __restrict__ k_equi, const float* __restrict__ k_inv,
                 const float* __restrict__ Wqi, const float* __restrict__ bqi,
                 const float* __restrict__ Wki, const float* __restrict__ bki,
                 const float* __restrict__ Wqe, const float* __restrict__ bqe,
                 const float* __restrict__ Wke, const float* __restrict__ bke,
                 const float* __restrict__ W1,  const float* __restrict__ b1,
                 const float* __restrict__ W2)
{
    const int side = blockIdx.y;
    const int tid  = threadIdx.x;

    if (side == 2) {
        // -------- weight prep: W1h (K=64 A-order [dot|dist]) + W2h --------
        const int idx = blockIdx.x * 256 + tid;
        if (idx < 128*36) {
            const int n = idx / 36, kq = idx % 36;
            float a = 0.f, b = 0.f;
            if (kq < 32) {
                a = W1[(size_t)(64 + 2*kq    ) * 128 + n];
                b = W1[(size_t)(64 + 2*kq + 1) * 128 + n];
            }
            g_W1h[n*36 + kq] = pack2(a, b);
        } else if (idx < 128*36 + 64*68) {
            const int j = idx - 128*36;
            const int n = j / 68, kq = j % 68;
            float a = 0.f, b = 0.f;
            if (kq < 64) {
                a = W2[(size_t)(2*kq    ) * 64 + n];
                b = W2[(size_t)(2*kq + 1) * 64 + n];
            }
            g_W2h[n*68 + kq] = pack2(a, b);
        }
        return;
    }

    extern __shared__ float ps[];
    float* sWe = ps + P_WE;
    float* sWi = ps + P_WI;
    float* sW1s = ps + P_W1S;
    float* sXE = ps + P_XE;
    float* sXI = ps + P_XI;
    float* sPI = ps + P_PI;
    float* sBE = ps + P_BE;
    float* sBI = ps + P_BI;
    float* sB1 = ps + P_B1;

    const float* xe = side ? k_equi : q_equi;
    const float* xi = side ? k_inv  : q_inv;
    const float* We = side ? Wke : Wqe;
    const float* be = side ? bke : bqe;
    const float* Wi = side ? Wki : Wqi;
    const float* bi = side ? bki : bqi;

    // ---- load weights to smem once per block ----
    {
        float4* d = (float4*)sWe; const float4* s = (const float4*)We;
        for (int i = tid; i < 2048; i += 256) d[i] = s[i];
        d = (float4*)sWi; s = (const float4*)Wi;
        for (int i = tid; i < 2048; i += 256) d[i] = s[i];
        // W1 slice: side 0 -> rows 0..31 ; side 1 -> rows 32..63
        d = (float4*)sW1s; s = (const float4*)(W1 + (side ? 32*128 : 0));
        for (int i = tid; i < 1024; i += 256) d[i] = s[i];
        if (!side)
            for (int i = tid; i < 128; i += 256) sB1[i] = b1[i];
        if (tid < 32)       sBE[tid] = be[tid];
        else if (tid < 64)  sBI[tid - 32] = bi[tid - 32];
    }
    __syncthreads();

    const int half = tid >> 7;           // two rows in flight
    const int ltid = tid & 127;
    const int rbase = blockIdx.x * ROWS_PER_BLK;

    #pragma unroll 1
    for (int rp = 0; rp < ROWS_PER_BLK / 2; rp++) {
        const int r  = rbase + rp * 2 + half;       // global row: b*768 + n
        const int bb = r >= 768 ? 1 : 0;
        const int n  = r - bb * 768;

        // ---- stream this row's inputs ----
        {
            const float* src = xe + (size_t)r * 768;
            #pragma unroll
            for (int i = 0; i < 6; i++) sXE[half * 768 + ltid + i * 128] = src[ltid + i * 128];
            const float* si = xi + (size_t)r * 256;
            #pragma unroll
            for (int i = 0; i < 2; i++) sXI[half * 256 + ltid + i * 128] = si[ltid + i * 128];
        }
        __syncthreads();

        // ---- projections ----
        if (ltid < 96) {
            const int c = ltid >> 5, m = ltid & 31;
            float acc = sBE[m];
            #pragma unroll 4
            for (int d = 0; d < 256; d++)
                acc = fmaf(sXE[half * 768 + c * 256 + d], sWe[d * 32 + m], acc);
            if (side) g_keT[((size_t)bb * 96 + ltid) * NK_ + n] = acc;   // transposed
            else      g_qe [(size_t)r * 96 + ltid] = acc;
        } else {
            const int m = ltid - 96;
            float acc = sBI[m];
            #pragma unroll 4
            for (int d = 0; d < 256; d++)
                acc = fmaf(sXI[half * 256 + d], sWi[d * 32 + m], acc);
            sPI[half * 32 + m] = acc;
        }
        __syncthreads();

        if (side) {
            // Bk[f] = ki @ W1[32:64]  (fp32 accumulate, pack fp16 pairs)
            // ltid < 64 covers f = 2*ltid, 2*ltid+1  (128 features = 64 half2)
            if (ltid < 64) {
                float a0 = 0.f, a1 = 0.f;
                #pragma unroll
                for (int m = 0; m < 32; m++) {
                    const float kv = sPI[half * 32 + m];
                    a0 = fmaf(kv, sW1s[m * 128 + 2*ltid],     a0);
                    a1 = fmaf(kv, sW1s[m * 128 + 2*ltid + 1], a1);
                }
                g_Bkh[((size_t)bb * NK_ + n) * 64 + ltid] = pack2(a0, a1);
            }
        } else {
            float acc = sB1[ltid];
            #pragma unroll
            for (int m = 0; m < 32; m++)
                acc = fmaf(sPI[half * 32 + m], sW1s[m * 128 + ltid], acc);
            g_Aq[(size_t)r * 128 + ltid] = acc;
        }
        __syncthreads();   // sXE/sXI/sPI reuse next iteration
    }
}

// =====================================================================
// Kernel B: pairwise kernel, fragment-direct feats, ki via epilogue Bk.
//   CTA = 16 q-rows x 64 k-rows; 8 passes of (2q x 64k, M=128).
//   GEMM1: A=[dot|dist] (K=64) @ W1h ; epi: +Aq +Bk, silu ; GEMM2 (K=128)
// =====================================================================
__global__ __launch_bounds__(256, 2)
void pair_kernel(const float* __restrict__ b2g, float* __restrict__ out)
{
    extern __shared__ char sm[];
    __half*   sW1h = (__half*)(sm + O_W1H);
    __half*   sW2h = (__half*)(sm + O_W2H);
    float*    sKET = (float*)(sm + O_KET);
    uint32_t* sBKH = (uint32_t*)(sm + O_BKH);
    float*    sAQ  = (float*)(sm + O_AQ);
    float*    sQE  = (float*)(sm + O_QE);
    float*    sB2  = (float*)(sm + O_B2);

    const int tid = threadIdx.x;
    const int b   = blockIdx.z;
    const int k0  = blockIdx.x * 64;
    const int q0  = blockIdx.y * 16;

    // ---------------- phase 0: one-time loads ----------------
    {   // pre-packed fp16 weights: W1h 1152 f4, W2h 1088 f4
        float4* d1 = (float4*)sW1h; const float4* s1 = (const float4*)g_W1h;
        for (int i = tid; i < 1152; i += 256) d1[i] = s1[i];
        float4* d2 = (float4*)sW2h; const float4* s2 = (const float4*)g_W2h;
        for (int i = tid; i < 1088; i += 256) d2[i] = s2[i];
    }
    {   // keT: 96 rows x 16 f4, smem stride 68 floats
        for (int i = tid; i < 1536; i += 256) {
            const int row = i >> 4, c4 = i & 15;
            *(float4*)(sKET + row * 68 + c4 * 4) =
                *(const float4*)(g_keT + ((size_t)b * 96 + row) * NK_ + k0 + c4 * 4);
        }
    }
    {   // Bkh: 64 rows x 16 uint4 (64 u32), smem stride 68 u32
        for (int i = tid; i < 1024; i += 256) {
            const int row = i >> 4, c4 = i & 15;
            *(uint4*)(sBKH + row * 68 + c4 * 4) =
                *(const uint4*)(g_Bkh + ((size_t)b * NK_ + k0 + row) * 64 + c4 * 4);
        }
    }
    {   // qe: 16 rows = 384 f4 ; Aq: 16 rows = 512 f4
        for (int i = tid; i < 384; i += 256)
            ((float4*)sQE)[i] = *(const float4*)(g_qe + (size_t)(b * NQ_ + q0) * 96 + i * 4);
        for (int i = tid; i < 512; i += 256)
            ((float4*)sAQ)[i] = *(const float4*)(g_Aq + (size_t)(b * NQ_ + q0) * 128 + i * 4);
        if (tid >= 192 && tid < 256) sB2[tid - 192] = b2g[tid - 192];
    }
    __syncthreads();   // the ONLY barrier

    // ---------------- warp/lane geometry ----------------
    const int wid = tid >> 5, lane = tid & 31;
    const int grp = lane >> 2, tig = lane & 3;
    const int kbase = (wid & 3) * 16;
    const int kk1 = kbase + grp, kk2 = kbase + grp + 8;
    const int qq  = wid >> 2;

    const uint32_t sW1b = smem_u32(sW1h);
    const uint32_t sW2b = smem_u32(sW2h);

    const int brow = (lane & 7) + ((lane >> 4) << 3);
    const int bkof = ((lane >> 3) & 1) * 16;

    // ---------------- pass loop: 8 x (2q x 64k), no barriers ----------------
    #pragma unroll 1
    for (int pass = 0; pass < 8; pass++) {
        const int qrow = pass * 2 + qq;

        // ---- feats directly into GEMM1 A-fragments ----
        uint32_t aDot[2][4], aDist[2][4];
        {
            float dotv[2][8], d2v[2][8];
            #pragma unroll
            for (int j = 0; j < 8; j++) {
                const int m = 2 * tig + (j & 1) + (j >> 1) * 8;
                float dv0 = 0.f, dv1 = 0.f, s0 = 0.f, s1 = 0.f;
                #pragma unroll
                for (int c = 0; c < 3; c++) {
                    const int ch = c * 32 + m;
                    const float qv = sQE[qrow * 96 + ch];
                    const float k1 = sKET[ch * 68 + kk1];
                    const float k2 = sKET[ch * 68 + kk2];
                    dv0 = fmaf(qv, k1, dv0);
                    dv1 = fmaf(qv, k2, dv1);
                    const float e1 = qv - k1; s0 = fmaf(e1, e1, s0);
                    const float e2 = qv - k2; s1 = fmaf(e2, e2, s1);
                }
                dotv[0][j] = dv0; dotv[1][j] = dv1;
                d2v[0][j]  = s0;  d2v[1][j]  = s1;
            }
            #pragma unroll
            for (int ks = 0; ks < 2; ks++) {
                aDot[ks][0] = pack2(dotv[0][ks*4+0], dotv[0][ks*4+1]);
                aDot[ks][1] = pack2(dotv[1][ks*4+0], dotv[1][ks*4+1]);
                aDot[ks][2] = pack2(dotv[0][ks*4+2], dotv[0][ks*4+3]);
                aDot[ks][3] = pack2(dotv[1][ks*4+2], dotv[1][ks*4+3]);
                aDist[ks][0] = pack2(sqrtf(d2v[0][ks*4+0]), sqrtf(d2v[0][ks*4+1]));
                aDist[ks][1] = pack2(sqrtf(d2v[1][ks*4+0]), sqrtf(d2v[1][ks*4+1]));
                aDist[ks][2] = pack2(sqrtf(d2v[0][ks*4+2]), sqrtf(d2v[0][ks*4+3]));
                aDist[ks][3] = pack2(sqrtf(d2v[1][ks*4+2]), sqrtf(d2v[1][ks*4+3]));
            }
        }

        // ---- GEMM1: D1[16x128] = A(K=64, from regs) @ W1h ----
        float c1[16][4];
        #pragma unroll
        for (int nt = 0; nt < 16; nt++)
            #pragma unroll
            for (int j = 0; j < 4; j++) c1[nt][j] = 0.f;

        #pragma unroll
        for (int ks = 0; ks < 4; ks++) {
            const uint32_t* A = (ks < 2) ? aDot[ks] : aDist[ks-2];
            #pragma unroll
            for (int np = 0; np < 8; np++) {
                uint32_t bb[4];
                ldmx4(bb, sW1b + (np * 16 + brow) * 144 + ks * 32 + bkof);
                mma16816(c1[np * 2 + 0], A, bb[0], bb[1]);
                mma16816(c1[np * 2 + 1], A, bb[2], bb[3]);
            }
        }

        // ---- epilogue 1 (regs): +Aq +Bk, silu -> GEMM2 A-fragments ----
        uint32_t a2[8][4];
        #pragma unroll
        for (int kt = 0; kt < 8; kt++) {
            #pragma unroll
            for (int hnt = 0; hnt < 2; hnt++) {
                const int nt = kt * 2 + hnt;
                const int f  = nt * 8 + tig * 2;
                const float aq0 = sAQ[qrow * 128 + f];
                const float aq1 = sAQ[qrow * 128 + f + 1];
                const float2 bk1 = unpack2(sBKH[kk1 * 68 + nt * 4 + tig]);
                const float2 bk2 = unpack2(sBKH[kk2 * 68 + nt * 4 + tig]);
                const float v0 = silu_f(c1[nt][0] + aq0 + bk1.x);
                const float v1 = silu_f(c1[nt][1] + aq1 + bk1.y);
                const float v2 = silu_f(c1[nt][2] + aq0 + bk2.x);
                const float v3 = silu_f(c1[nt][3] + aq1 + bk2.y);
                a2[kt][hnt * 2 + 0] = pack2(v0, v1);
                a2[kt][hnt * 2 + 1] = pack2(v2, v3);
            }
        }

        // ---- GEMM2: D2[16x64] = H[16x128] @ W2 (A from registers) ----
        float c2[8][4];
        #pragma unroll
        for (int nt = 0; nt < 8; nt++)
            #pragma unroll
            for (int j = 0; j < 4; j++) c2[nt][j] = 0.f;

        #pragma unroll
        for (int ks = 0; ks < 8; ks++) {
            #pragma unroll
            for (int np = 0; np < 4; np++) {
                uint32_t bb[4];
                ldmx4(bb, sW2b + (np * 16 + brow) * 272 + ks * 32 + bkof);
                mma16816(c2[np * 2 + 0], a2[ks], bb[0], bb[1]);
                mma16816(c2[np * 2 + 1], a2[ks], bb[2], bb[3]);
            }
        }

        // ---- epilogue 2: +b2, store ----
        {
            const int q = q0 + qrow;
            #pragma unroll
            for (int h = 0; h < 2; h++) {
                const int kk = kbase + grp + h * 8;
                const size_t base = ((size_t)(b * NQ_ + q) * NK_ + k0 + kk) * 64;
                #pragma unroll
                for (int nt = 0; nt < 8; nt++) {
                    const int f = nt * 8 + tig * 2;
                    float2 v;
                    v.x = c2[nt][h * 2 + 0] + sB2[f];
                    v.y = c2[nt][h * 2 + 1] + sB2[f + 1];
                    *(float2*)&out[base + f] = v;
                }
            }
        }
    }
}

// =====================================================================
extern "C" void kernel_launch(void* const* d_in, const int* in_sizes, int n_in,
                              void* d_out, int out_size)
{
    (void)in_sizes; (void)n_in; (void)out_size;
    const float* q_equi = (const float*)d_in[0];
    const float* q_inv  = (const float*)d_in[1];
    const float* k_equi = (const float*)d_in[2];
    const float* k_inv  = (const float*)d_in[3];
    const float* Wqi = (const float*)d_in[4];  const float* bqi = (const float*)d_in[5];
    const float* Wki = (const float*)d_in[6];  const float* bki = (const float*)d_in[7];
    const float* Wqe = (const float*)d_in[8];  const float* bqe = (const float*)d_in[9];
    const float* Wke = (const float*)d_in[10]; const float* bke = (const float*)d_in[11];
    const float* W1  = (const float*)d_in[12]; const float* b1  = (const float*)d_in[13];
    const float* W2  = (const float*)d_in[14]; const float* b2  = (const float*)d_in[15];
    float* out = (float*)d_out;

    cudaFuncSetAttribute(proj_kernel, cudaFuncAttributeMaxDynamicSharedMemorySize, PROJ_SMEM);
    cudaFuncSetAttribute(pair_kernel, cudaFuncAttributeMaxDynamicSharedMemorySize, SMEM_TOTAL);

    proj_kernel<<<dim3(96, 3), 256, PROJ_SMEM>>>(q_equi, q_inv, k_equi, k_inv,
                                                 Wqi, bqi, Wki, bki,
                                                 Wqe, bqe, Wke, bke, W1, b1, W2);
    pair_kernel<<<dim3(NK_ / 64, NQ_ / 16, B_), 256, SMEM_TOTAL>>>(b2, out);
}

// round 14
// speedup vs baseline: 1.2812x; 1.0262x over previous
#include <cuda_runtime.h>
#include <cuda_fp16.h>
#include <stdint.h>
#include <stddef.h>

// ---------------- problem constants ----------------
#define B_    2
#define NQ_   768
#define NK_   768

// ---------------- static scratch ----------------
__device__ uint32_t g_qeh [B_*NQ_*48];      // [b,q][ch2] half2(qe[2ch2], qe[2ch2+1])
__device__ uint32_t g_keTh[B_*48*NK_];      // [b][ch2][k] half2(ke[2ch2], ke[2ch2+1])
__device__ float    g_Aq  [B_*NQ_*128];     // b1 + qi @ W1[0:32]
__device__ uint32_t g_Bkh [B_*NK_*64];      // [b,k][f2] half2 of Bk = ki@W1[32:64] (128 f)
__device__ uint32_t g_W1h [128*36];         // [n][kq] B-tile for A=[dot|dist] (K=64)
__device__ uint32_t g_W2h [64*68];          // [n][kq] half2{W2[2kq][n], W2[2kq+1][n]}

// ---------------- helpers ----------------
__device__ __forceinline__ uint32_t smem_u32(const void* p){
    uint32_t a;
    asm("{ .reg .u64 t; cvta.to.shared.u64 t, %1; cvt.u32.u64 %0, t; }" : "=r"(a) : "l"(p));
    return a;
}
__device__ __forceinline__ float tanh_ap(float x){
    float y; asm("tanh.approx.f32 %0, %1;" : "=f"(y) : "f"(x)); return y;
}
__device__ __forceinline__ float silu_f(float v){
    const float hv = 0.5f * v;
    return fmaf(hv, tanh_ap(hv), hv);          // v * sigmoid(v)
}
__device__ __forceinline__ uint32_t pack2(float a, float b){
    __half2 h = __floats2half2_rn(a, b);
    return *(const uint32_t*)&h;
}
__device__ __forceinline__ float2 unpack2(uint32_t u){
    return __half22float2(*(__half2*)&u);
}
__device__ __forceinline__ void ldmx4(uint32_t* r, uint32_t addr){
    asm volatile("ldmatrix.sync.aligned.m8n8.x4.shared.b16 {%0,%1,%2,%3}, [%4];"
        : "=r"(r[0]), "=r"(r[1]), "=r"(r[2]), "=r"(r[3]) : "r"(addr));
}
__device__ __forceinline__ void mma16816(float* d, const uint32_t* a, uint32_t b0, uint32_t b1){
    asm volatile(
        "mma.sync.aligned.m16n8k16.row.col.f32.f16.f16.f32 "
        "{%0,%1,%2,%3}, {%4,%5,%6,%7}, {%8,%9}, {%0,%1,%2,%3};"
        : "+f"(d[0]), "+f"(d[1]), "+f"(d[2]), "+f"(d[3])
        : "r"(a[0]), "r"(a[1]), "r"(a[2]), "r"(a[3]), "r"(b0), "r"(b1));
}

// ---------------- pair-kernel smem layout (bytes) ----------------
#define O_W1H  0                // [128 n][72 k] fp16, stride 144B    = 18432
#define O_W2H  18432            // [ 64 n][136 k] fp16, stride 272B   = 17408
#define O_KETH 35840            // [48 ch2][68 kk] u32 (stride 68)    = 13056
#define O_BKH  48896            // [64 kk][68 f2] u32 (stride 68)     = 17408
#define O_AQ   66304            // [16][128] fp32                     = 8192
#define O_QEH  74496            // [16][48] u32                       = 3072
#define O_B2   77568            // [64] fp32                          = 256
#define SMEM_TOTAL 77824

// ---------------- proj-kernel smem layout (floats) ----------------
#define P_WE   0                // [256*32]                           = 8192 f
#define P_WI   8192             // [256*32]                           = 8192 f
#define P_W1S  16384            // [32*128]                           = 4096 f
#define P_XE   20480            // [2][768]                           = 1536 f
#define P_XI   22016            // [2][256]                           =  512 f
#define P_PI   22528            // [2][32]                            =   64 f
#define P_EQ   22592            // [2][96]                            =  192 f
#define P_BE   22784            // [32]
#define P_BI   22816            // [32]
#define P_B1   22848            // [128]
#define PROJ_FLOATS 22976
#define PROJ_SMEM (PROJ_FLOATS * 4)
#define ROWS_PER_BLK 8

// =====================================================================
// Kernel P: projections (sides 0/1, 8 rows/block, weights in smem)
//           + weight prep (side 2).  grid (192, 3) x 256.
//   side 0: qeh (fp16-packed), Aq = b1 + qi@W1[0:32]
//   side 1: keTh (fp16-packed, transposed), Bkh = fp16 ki@W1[32:64]
// =====================================================================
__global__ __launch_bounds__(256)
void proj_kernel(const float* __restrict__ q_equi, const float* __restrict__ q_inv,
                 const float* __restrict__ k_equi, const float* __restrict__ k_inv,
                 const float* __restrict__ Wqi, const float* __restrict__ bqi,
                 const float* __restrict__ Wki, const float* __restrict__ bki,
                 const float* __restrict__ Wqe, const float* __restrict__ bqe,
                 const float* __restrict__ Wke, const float* __restrict__ bke,
                 const float* __restrict__ W1,  const float* __restrict__ b1,
                 const float* __restrict__ W2)
{
    const int side = blockIdx.y;
    const int tid  = threadIdx.x;

    if (side == 2) {
        // -------- weight prep: W1h (K=64 A-order [dot|dist]) + W2h --------
        const int idx = blockIdx.x * 256 + tid;
        if (idx < 128*36) {
            const int n = idx / 36, kq = idx % 36;
            float a = 0.f, b = 0.f;
            if (kq < 32) {
                a = W1[(size_t)(64 + 2*kq    ) * 128 + n];
                b = W1[(size_t)(64 + 2*kq + 1) * 128 + n];
            }
            g_W1h[n*36 + kq] = pack2(a, b);
        } else if (idx < 128*36 + 64*68) {
            const int j = idx - 128*36;
            const int n = j / 68, kq = j % 68;
            float a = 0.f, b = 0.f;
            if (kq < 64) {
                a = W2[(size_t)(2*kq    ) * 64 + n];
                b = W2[(size_t)(2*kq + 1) * 64 + n];
            }
            g_W2h[n*68 + kq] = pack2(a, b);
        }
        return;
    }

    extern __shared__ float ps[];
    float* sWe = ps + P_WE;
    float* sWi = ps + P_WI;
    float* sW1s = ps + P_W1S;
    float* sXE = ps + P_XE;
    float* sXI = ps + P_XI;
    float* sPI = ps + P_PI;
    float* sEQ = ps + P_EQ;
    float* sBE = ps + P_BE;
    float* sBI = ps + P_BI;
    float* sB1 = ps + P_B1;

    const float* xe = side ? k_equi : q_equi;
    const float* xi = side ? k_inv  : q_inv;
    const float* We = side ? Wke : Wqe;
    const float* be = side ? bke : bqe;
    const float* Wi = side ? Wki : Wqi;
    const float* bi = side ? bki : bqi;

    // ---- load weights to smem once per block ----
    {
        float4* d = (float4*)sWe; const float4* s = (const float4*)We;
        for (int i = tid; i < 2048; i += 256) d[i] = s[i];
        d = (float4*)sWi; s = (const float4*)Wi;
        for (int i = tid; i < 2048; i += 256) d[i] = s[i];
        // W1 slice: side 0 -> rows 0..31 ; side 1 -> rows 32..63
        d = (float4*)sW1s; s = (const float4*)(W1 + (side ? 32*128 : 0));
        for (int i = tid; i < 1024; i += 256) d[i] = s[i];
        if (!side)
            for (int i = tid; i < 128; i += 256) sB1[i] = b1[i];
        if (tid < 32)       sBE[tid] = be[tid];
        else if (tid < 64)  sBI[tid - 32] = bi[tid - 32];
    }
    __syncthreads();

    const int half = tid >> 7;           // two rows in flight
    const int ltid = tid & 127;
    const int rbase = blockIdx.x * ROWS_PER_BLK;

    #pragma unroll 1
    for (int rp = 0; rp < ROWS_PER_BLK / 2; rp++) {
        const int r  = rbase + rp * 2 + half;       // global row: b*768 + n
        const int bb = r >= 768 ? 1 : 0;
        const int n  = r - bb * 768;

        // ---- stream this row's inputs ----
        {
            const float* src = xe + (size_t)r * 768;
            #pragma unroll
            for (int i = 0; i < 6; i++) sXE[half * 768 + ltid + i * 128] = src[ltid + i * 128];
            const float* si = xi + (size_t)r * 256;
            #pragma unroll
            for (int i = 0; i < 2; i++) sXI[half * 256 + ltid + i * 128] = si[ltid + i * 128];
        }
        __syncthreads();

        // ---- projections ----
        if (ltid < 96) {
            const int c = ltid >> 5, m = ltid & 31;
            float acc = sBE[m];
            #pragma unroll 4
            for (int d = 0; d < 256; d++)
                acc = fmaf(sXE[half * 768 + c * 256 + d], sWe[d * 32 + m], acc);
            sEQ[half * 96 + ltid] = acc;
        } else {
            const int m = ltid - 96;
            float acc = sBI[m];
            #pragma unroll 4
            for (int d = 0; d < 256; d++)
                acc = fmaf(sXI[half * 256 + d], sWi[d * 32 + m], acc);
            sPI[half * 32 + m] = acc;
        }
        __syncthreads();

        if (side) {
            // pack keTh pairs
            if (ltid < 48)
                g_keTh[((size_t)bb * 48 + ltid) * NK_ + n] =
                    pack2(sEQ[half * 96 + 2*ltid], sEQ[half * 96 + 2*ltid + 1]);
            // Bk[f] = ki @ W1[32:64]  (fp32 accumulate, pack fp16 pairs)
            if (ltid < 64) {
                float a0 = 0.f, a1 = 0.f;
                #pragma unroll
                for (int m = 0; m < 32; m++) {
                    const float kv = sPI[half * 32 + m];
                    a0 = fmaf(kv, sW1s[m * 128 + 2*ltid],     a0);
                    a1 = fmaf(kv, sW1s[m * 128 + 2*ltid + 1], a1);
                }
                g_Bkh[((size_t)bb * NK_ + n) * 64 + ltid] = pack2(a0, a1);
            }
        } else {
            if (ltid < 48)
                g_qeh[(size_t)r * 48 + ltid] =
                    pack2(sEQ[half * 96 + 2*ltid], sEQ[half * 96 + 2*ltid + 1]);
            float acc = sB1[ltid];
            #pragma unroll
            for (int m = 0; m < 32; m++)
                acc = fmaf(sPI[half * 32 + m], sW1s[m * 128 + ltid], acc);
            g_Aq[(size_t)r * 128 + ltid] = acc;
        }
        __syncthreads();   // buffers reused next iteration
    }
}

// =====================================================================
// Kernel B: pairwise kernel, fragment-direct feats (fp16-packed inputs).
//   CTA = 16 q-rows x 64 k-rows; 8 passes of (2q x 64k, M=128).
//   GEMM1: A=[dot|dist] (K=64) @ W1h ; epi: +Aq +Bk, silu ; GEMM2 (K=128)
// =====================================================================
__global__ __launch_bounds__(256, 2)
void pair_kernel(const float* __restrict__ b2g, float* __restrict__ out)
{
    extern __shared__ char sm[];
    __half*   sW1h  = (__half*)(sm + O_W1H);
    __half*   sW2h  = (__half*)(sm + O_W2H);
    uint32_t* sKETH = (uint32_t*)(sm + O_KETH);
    uint32_t* sBKH  = (uint32_t*)(sm + O_BKH);
    float*    sAQ   = (float*)(sm + O_AQ);
    uint32_t* sQEH  = (uint32_t*)(sm + O_QEH);
    float*    sB2   = (float*)(sm + O_B2);

    const int tid = threadIdx.x;
    const int b   = blockIdx.z;
    const int k0  = blockIdx.x * 64;
    const int q0  = blockIdx.y * 16;

    // ---------------- phase 0: one-time loads ----------------
    {   // pre-packed fp16 weights: W1h 1152 f4, W2h 1088 f4
        float4* d1 = (float4*)sW1h; const float4* s1 = (const float4*)g_W1h;
        for (int i = tid; i < 1152; i += 256) d1[i] = s1[i];
        float4* d2 = (float4*)sW2h; const float4* s2 = (const float4*)g_W2h;
        for (int i = tid; i < 1088; i += 256) d2[i] = s2[i];
    }
    {   // keTh: 48 rows x 16 uint4 (64 u32), smem stride 68 u32
        for (int i = tid; i < 768; i += 256) {
            const int row = i >> 4, c4 = i & 15;
            *(uint4*)(sKETH + row * 68 + c4 * 4) =
                *(const uint4*)(g_keTh + ((size_t)b * 48 + row) * NK_ + k0 + c4 * 4);
        }
    }
    {   // Bkh: 64 rows x 16 uint4 (64 u32), smem stride 68 u32
        for (int i = tid; i < 1024; i += 256) {
            const int row = i >> 4, c4 = i & 15;
            *(uint4*)(sBKH + row * 68 + c4 * 4) =
                *(const uint4*)(g_Bkh + ((size_t)b * NK_ + k0 + row) * 64 + c4 * 4);
        }
    }
    {   // qeh: 16 rows x 48 u32 = 192 uint4 (contiguous) ; Aq: 512 f4
        for (int i = tid; i < 192; i += 256)
            ((uint4*)sQEH)[i] = *(const uint4*)(g_qeh + (size_t)(b * NQ_ + q0) * 48 + i * 4);
        for (int i = tid; i < 512; i += 256)
            ((float4*)sAQ)[i] = *(const float4*)(g_Aq + (size_t)(b * NQ_ + q0) * 128 + i * 4);
        if (tid >= 192 && tid < 256) sB2[tid - 192] = b2g[tid - 192];
    }
    __syncthreads();   // the ONLY barrier

    // ---------------- warp/lane geometry ----------------
    const int wid = tid >> 5, lane = tid & 31;
    const int grp = lane >> 2, tig = lane & 3;
    const int kbase = (wid & 3) * 16;
    const int kk1 = kbase + grp, kk2 = kbase + grp + 8;
    const int qq  = wid >> 2;

    const uint32_t sW1b = smem_u32(sW1h);
    const uint32_t sW2b = smem_u32(sW2h);

    const int brow = (lane & 7) + ((lane >> 4) << 3);
    const int bkof = ((lane >> 3) & 1) * 16;

    // ---------------- pass loop: 8 x (2q x 64k), no barriers ----------------
    #pragma unroll 1
    for (int pass = 0; pass < 8; pass++) {
        const int qrow = pass * 2 + qq;

        // ---- feats directly into GEMM1 A-fragments (fp16-packed inputs) ----
        uint32_t aDot[2][4], aDist[2][4];
        {
            float dotv[2][8], d2v[2][8];
            #pragma unroll
            for (int jj = 0; jj < 4; jj++) {
                float dv00 = 0.f, dv01 = 0.f, dv10 = 0.f, dv11 = 0.f;
                float sv00 = 0.f, sv01 = 0.f, sv10 = 0.f, sv11 = 0.f;
                #pragma unroll
                for (int c = 0; c < 3; c++) {
                    const int ch2 = c * 16 + tig + 4 * jj;
                    const float2 q2 = unpack2(sQEH[qrow * 48 + ch2]);
                    const float2 k1 = unpack2(sKETH[ch2 * 68 + kk1]);
                    const float2 k2 = unpack2(sKETH[ch2 * 68 + kk2]);
                    dv00 = fmaf(q2.x, k1.x, dv00);
                    dv01 = fmaf(q2.y, k1.y, dv01);
                    dv10 = fmaf(q2.x, k2.x, dv10);
                    dv11 = fmaf(q2.y, k2.y, dv11);
                    float e;
                    e = q2.x - k1.x; sv00 = fmaf(e, e, sv00);
                    e = q2.y - k1.y; sv01 = fmaf(e, e, sv01);
                    e = q2.x - k2.x; sv10 = fmaf(e, e, sv10);
                    e = q2.y - k2.y; sv11 = fmaf(e, e, sv11);
                }
                dotv[0][2*jj] = dv00; dotv[0][2*jj+1] = dv01;
                dotv[1][2*jj] = dv10; dotv[1][2*jj+1] = dv11;
                d2v[0][2*jj]  = sv00; d2v[0][2*jj+1]  = sv01;
                d2v[1][2*jj]  = sv10; d2v[1][2*jj+1]  = sv11;
            }
            #pragma unroll
            for (int ks = 0; ks < 2; ks++) {
                aDot[ks][0] = pack2(dotv[0][ks*4+0], dotv[0][ks*4+1]);
                aDot[ks][1] = pack2(dotv[1][ks*4+0], dotv[1][ks*4+1]);
                aDot[ks][2] = pack2(dotv[0][ks*4+2], dotv[0][ks*4+3]);
                aDot[ks][3] = pack2(dotv[1][ks*4+2], dotv[1][ks*4+3]);
                aDist[ks][0] = pack2(sqrtf(d2v[0][ks*4+0]), sqrtf(d2v[0][ks*4+1]));
                aDist[ks][1] = pack2(sqrtf(d2v[1][ks*4+0]), sqrtf(d2v[1][ks*4+1]));
                aDist[ks][2] = pack2(sqrtf(d2v[0][ks*4+2]), sqrtf(d2v[0][ks*4+3]));
                aDist[ks][3] = pack2(sqrtf(d2v[1][ks*4+2]), sqrtf(d2v[1][ks*4+3]));
            }
        }

        // ---- GEMM1: D1[16x128] = A(K=64, from regs) @ W1h ----
        float c1[16][4];
        #pragma unroll
        for (int nt = 0; nt < 16; nt++)
            #pragma unroll
            for (int j = 0; j < 4; j++) c1[nt][j] = 0.f;

        #pragma unroll
        for (int ks = 0; ks < 4; ks++) {
            const uint32_t* A = (ks < 2) ? aDot[ks] : aDist[ks-2];
            #pragma unroll
            for (int np = 0; np < 8; np++) {
                uint32_t bb[4];
                ldmx4(bb, sW1b + (np * 16 + brow) * 144 + ks * 32 + bkof);
                mma16816(c1[np * 2 + 0], A, bb[0], bb[1]);
                mma16816(c1[np * 2 + 1], A, bb[2], bb[3]);
            }
        }

        // ---- epilogue 1 (regs): +Aq +Bk, silu -> GEMM2 A-fragments ----
        uint32_t a2[8][4];
        #pragma unroll
        for (int kt = 0; kt < 8; kt++) {
            #pragma unroll
            for (int hnt = 0; hnt < 2; hnt++) {
                const int nt = kt * 2 + hnt;
                const int f  = nt * 8 + tig * 2;
                const float aq0 = sAQ[qrow * 128 + f];
                const float aq1 = sAQ[qrow * 128 + f + 1];
                const float2 bk1 = unpack2(sBKH[kk1 * 68 + nt * 4 + tig]);
                const float2 bk2 = unpack2(sBKH[kk2 * 68 + nt * 4 + tig]);
                const float v0 = silu_f(c1[nt][0] + aq0 + bk1.x);
                const float v1 = silu_f(c1[nt][1] + aq1 + bk1.y);
                const float v2 = silu_f(c1[nt][2] + aq0 + bk2.x);
                const float v3 = silu_f(c1[nt][3] + aq1 + bk2.y);
                a2[kt][hnt * 2 + 0] = pack2(v0, v1);
                a2[kt][hnt * 2 + 1] = pack2(v2, v3);
            }
        }

        // ---- GEMM2: D2[16x64] = H[16x128] @ W2 (A from registers) ----
        float c2[8][4];
        #pragma unroll
        for (int nt = 0; nt < 8; nt++)
            #pragma unroll
            for (int j = 0; j < 4; j++) c2[nt][j] = 0.f;

        #pragma unroll
        for (int ks = 0; ks < 8; ks++) {
            #pragma unroll
            for (int np = 0; np < 4; np++) {
                uint32_t bb[4];
                ldmx4(bb, sW2b + (np * 16 + brow) * 272 + ks * 32 + bkof);
                mma16816(c2[np * 2 + 0], a2[ks], bb[0], bb[1]);
                mma16816(c2[np * 2 + 1], a2[ks], bb[2], bb[3]);
            }
        }

        // ---- epilogue 2: +b2, store ----
        {
            const int q = q0 + qrow;
            #pragma unroll
            for (int h = 0; h < 2; h++) {
                const int kk = kbase + grp + h * 8;
                const size_t base = ((size_t)(b * NQ_ + q) * NK_ + k0 + kk) * 64;
                #pragma unroll
                for (int nt = 0; nt < 8; nt++) {
                    const int f = nt * 8 + tig * 2;
                    float2 v;
                    v.x = c2[nt][h * 2 + 0] + sB2[f];
                    v.y = c2[nt][h * 2 + 1] + sB2[f + 1];
                    *(float2*)&out[base + f] = v;
                }
            }
        }
    }
}

// =====================================================================
extern "C" void kernel_launch(void* const* d_in, const int* in_sizes, int n_in,
                              void* d_out, int out_size)
{
    (void)in_sizes; (void)n_in; (void)out_size;
    const float* q_equi = (const float*)d_in[0];
    const float* q_inv  = (const float*)d_in[1];
    const float* k_equi = (const float*)d_in[2];
    const float* k_inv  = (const float*)d_in[3];
    const float* Wqi = (const float*)d_in[4];  const float* bqi = (const float*)d_in[5];
    const float* Wki = (const float*)d_in[6];  const float* bki = (const float*)d_in[7];
    const float* Wqe = (const float*)d_in[8];  const float* bqe = (const float*)d_in[9];
    const float* Wke = (const float*)d_in[10]; const float* bke = (const float*)d_in[11];
    const float* W1  = (const float*)d_in[12]; const float* b1  = (const float*)d_in[13];
    const float* W2  = (const float*)d_in[14]; const float* b2  = (const float*)d_in[15];
    float* out = (float*)d_out;

    cudaFuncSetAttribute(proj_kernel, cudaFuncAttributeMaxDynamicSharedMemorySize, PROJ_SMEM);
    cudaFuncSetAttribute(pair_kernel, cudaFuncAttributeMaxDynamicSharedMemorySize, SMEM_TOTAL);

    proj_kernel<<<dim3(192, 3), 256, PROJ_SMEM>>>(q_equi, q_inv, k_equi, k_inv,
                                                  Wqi, bqi, Wki, bki,
                                                  Wqe, bqe, Wke, bke, W1, b1, W2);
    pair_kernel<<<dim3(NK_ / 64, NQ_ / 16, B_), 256, SMEM_TOTAL>>>(b2, out);
}

// round 15
// speedup vs baseline: 1.2953x; 1.0110x over previous
#include <cuda_runtime.h>
#include <cuda_fp16.h>
#include <stdint.h>
#include <stddef.h>

// ---------------- problem constants ----------------
#define B_    2
#define NQ_   768
#define NK_   768

// ---------------- static scratch ----------------
__device__ uint32_t g_qeh [B_*NQ_*48];      // [b,q][ch2] half2(qe[2ch2], qe[2ch2+1])
__device__ uint32_t g_keTh[B_*48*NK_];      // [b][ch2][k] half2(ke[2ch2], ke[2ch2+1])
__device__ uint32_t g_Aqh [B_*NQ_*64];      // [b,q][f2] half2 of Aq = b1 + qi@W1[0:32]
__device__ uint32_t g_Bkh [B_*NK_*64];      // [b,k][f2] half2 of Bk = ki@W1[32:64]
__device__ uint32_t g_W1h [128*36];         // [n][kq] B-tile for A=[dot|dist] (K=64)
__device__ uint32_t g_W2h [64*68];          // [n][kq] half2{W2[2kq][n], W2[2kq+1][n]}

// ---------------- helpers ----------------
__device__ __forceinline__ uint32_t smem_u32(const void* p){
    uint32_t a;
    asm("{ .reg .u64 t; cvta.to.shared.u64 t, %1; cvt.u32.u64 %0, t; }" : "=r"(a) : "l"(p));
    return a;
}
__device__ __forceinline__ float tanh_ap(float x){
    float y; asm("tanh.approx.f32 %0, %1;" : "=f"(y) : "f"(x)); return y;
}
__device__ __forceinline__ float sqrt_ap(float x){
    float y; asm("sqrt.approx.f32 %0, %1;" : "=f"(y) : "f"(x)); return y;
}
__device__ __forceinline__ float silu_f(float v){
    const float hv = 0.5f * v;
    return fmaf(hv, tanh_ap(hv), hv);          // v * sigmoid(v)
}
__device__ __forceinline__ uint32_t pack2(float a, float b){
    __half2 h = __floats2half2_rn(a, b);
    return *(const uint32_t*)&h;
}
__device__ __forceinline__ float2 unpack2(uint32_t u){
    return __half22float2(*(__half2*)&u);
}
__device__ __forceinline__ void ldmx4(uint32_t* r, uint32_t addr){
    asm volatile("ldmatrix.sync.aligned.m8n8.x4.shared.b16 {%0,%1,%2,%3}, [%4];"
        : "=r"(r[0]), "=r"(r[1]), "=r"(r[2]), "=r"(r[3]) : "r"(addr));
}
__device__ __forceinline__ void mma16816(float* d, const uint32_t* a, uint32_t b0, uint32_t b1){
    asm volatile(
        "mma.sync.aligned.m16n8k16.row.col.f32.f16.f16.f32 "
        "{%0,%1,%2,%3}, {%4,%5,%6,%7}, {%8,%9}, {%0,%1,%2,%3};"
        : "+f"(d[0]), "+f"(d[1]), "+f"(d[2]), "+f"(d[3])
        : "r"(a[0]), "r"(a[1]), "r"(a[2]), "r"(a[3]), "r"(b0), "r"(b1));
}

// ---------------- pair-kernel smem layout (bytes) ----------------
#define O_W1H  0                // [128 n][72 k] fp16, stride 144B    = 18432
#define O_W2H  18432            // [ 64 n][136 k] fp16, stride 272B   = 17408
#define O_KETH 35840            // [48 ch2][68 kk] u32 (stride 68)    = 13056
#define O_BKH  48896            // [64 kk][68 f2] u32 (stride 68)     = 17408
#define O_AQH  66304            // [16][64] u32                       = 4096
#define O_QEH  70400            // [16][48] u32                       = 3072
#define O_B2   73472            // [64] fp32                          = 256
#define SMEM_TOTAL 73728

// ---------------- proj-kernel smem layout (floats) ----------------
#define P_WE   0                // [256*32]                           = 8192 f
#define P_WI   8192             // [256*32]                           = 8192 f
#define P_W1S  16384            // [32*128]                           = 4096 f
#define P_XE   20480            // [2][768]                           = 1536 f
#define P_XI   22016            // [2][256]                           =  512 f
#define P_PI   22528            // [2][32]                            =   64 f
#define P_EQ   22592            // [2][96]                            =  192 f
#define P_BE   22784            // [32]
#define P_BI   22816            // [32]
#define P_B1   22848            // [128]
#define PROJ_FLOATS 22976
#define PROJ_SMEM (PROJ_FLOATS * 4)
#define ROWS_PER_BLK 8

// =====================================================================
// Kernel P: projections (sides 0/1, 8 rows/block, weights in smem)
//           + weight prep (side 2).  grid (192, 3) x 256.
// =====================================================================
__global__ __launch_bounds__(256)
void proj_kernel(const float* __restrict__ q_equi, const float* __restrict__ q_inv,
                 const float* __restrict__ k_equi, const float* __restrict__ k_inv,
                 const float* __restrict__ Wqi, const float* __restrict__ bqi,
                 const float* __restrict__ Wki, const float* __restrict__ bki,
                 const float* __restrict__ Wqe, const float* __restrict__ bqe,
                 const float* __restrict__ Wke, const float* __restrict__ bke,
                 const float* __restrict__ W1,  const float* __restrict__ b1,
                 const float* __restrict__ W2)
{
    const int side = blockIdx.y;
    const int tid  = threadIdx.x;

    if (side == 2) {
        // -------- weight prep: W1h (K=64 A-order [dot|dist]) + W2h --------
        const int idx = blockIdx.x * 256 + tid;
        if (idx < 128*36) {
            const int n = idx / 36, kq = idx % 36;
            float a = 0.f, b = 0.f;
            if (kq < 32) {
                a = W1[(size_t)(64 + 2*kq    ) * 128 + n];
                b = W1[(size_t)(64 + 2*kq + 1) * 128 + n];
            }
            g_W1h[n*36 + kq] = pack2(a, b);
        } else if (idx < 128*36 + 64*68) {
            const int j = idx - 128*36;
            const int n = j / 68, kq = j % 68;
            float a = 0.f, b = 0.f;
            if (kq < 64) {
                a = W2[(size_t)(2*kq    ) * 64 + n];
                b = W2[(size_t)(2*kq + 1) * 64 + n];
            }
            g_W2h[n*68 + kq] = pack2(a, b);
        }
        return;
    }

    extern __shared__ float ps[];
    float* sWe = ps + P_WE;
    float* sWi = ps + P_WI;
    float* sW1s = ps + P_W1S;
    float* sXE = ps + P_XE;
    float* sXI = ps + P_XI;
    float* sPI = ps + P_PI;
    float* sEQ = ps + P_EQ;
    float* sBE = ps + P_BE;
    float* sBI = ps + P_BI;
    float* sB1 = ps + P_B1;

    const float* xe = side ? k_equi : q_equi;
    const float* xi = side ? k_inv  : q_inv;
    const float* We = side ? Wke : Wqe;
    const float* be = side ? bke : bqe;
    const float* Wi = side ? Wki : Wqi;
    const float* bi = side ? bki : bqi;

    // ---- load weights to smem once per block ----
    {
        float4* d = (float4*)sWe; const float4* s = (const float4*)We;
        for (int i = tid; i < 2048; i += 256) d[i] = s[i];
        d = (float4*)sWi; s = (const float4*)Wi;
        for (int i = tid; i < 2048; i += 256) d[i] = s[i];
        // W1 slice: side 0 -> rows 0..31 ; side 1 -> rows 32..63
        d = (float4*)sW1s; s = (const float4*)(W1 + (side ? 32*128 : 0));
        for (int i = tid; i < 1024; i += 256) d[i] = s[i];
        if (!side)
            for (int i = tid; i < 128; i += 256) sB1[i] = b1[i];
        if (tid < 32)       sBE[tid] = be[tid];
        else if (tid < 64)  sBI[tid - 32] = bi[tid - 32];
    }
    __syncthreads();

    const int half = tid >> 7;           // two rows in flight
    const int ltid = tid & 127;
    const int rbase = blockIdx.x * ROWS_PER_BLK;

    #pragma unroll 1
    for (int rp = 0; rp < ROWS_PER_BLK / 2; rp++) {
        const int r  = rbase + rp * 2 + half;       // global row: b*768 + n
        const int bb = r >= 768 ? 1 : 0;
        const int n  = r - bb * 768;

        // ---- stream this row's inputs ----
        {
            const float* src = xe + (size_t)r * 768;
            #pragma unroll
            for (int i = 0; i < 6; i++) sXE[half * 768 + ltid + i * 128] = src[ltid + i * 128];
            const float* si = xi + (size_t)r * 256;
            #pragma unroll
            for (int i = 0; i < 2; i++) sXI[half * 256 + ltid + i * 128] = si[ltid + i * 128];
        }
        __syncthreads();

        // ---- projections (4-way split accumulators: chain depth 64) ----
        if (ltid < 96) {
            const int c = ltid >> 5, m = ltid & 31;
            float a0 = sBE[m], a1 = 0.f, a2 = 0.f, a3 = 0.f;
            #pragma unroll 4
            for (int d = 0; d < 256; d += 4) {
                a0 = fmaf(sXE[half * 768 + c * 256 + d    ], sWe[(d    ) * 32 + m], a0);
                a1 = fmaf(sXE[half * 768 + c * 256 + d + 1], sWe[(d + 1) * 32 + m], a1);
                a2 = fmaf(sXE[half * 768 + c * 256 + d + 2], sWe[(d + 2) * 32 + m], a2);
                a3 = fmaf(sXE[half * 768 + c * 256 + d + 3], sWe[(d + 3) * 32 + m], a3);
            }
            sEQ[half * 96 + ltid] = (a0 + a1) + (a2 + a3);
        } else {
            const int m = ltid - 96;
            float a0 = sBI[m], a1 = 0.f, a2 = 0.f, a3 = 0.f;
            #pragma unroll 4
            for (int d = 0; d < 256; d += 4) {
                a0 = fmaf(sXI[half * 256 + d    ], sWi[(d    ) * 32 + m], a0);
                a1 = fmaf(sXI[half * 256 + d + 1], sWi[(d + 1) * 32 + m], a1);
                a2 = fmaf(sXI[half * 256 + d + 2], sWi[(d + 2) * 32 + m], a2);
                a3 = fmaf(sXI[half * 256 + d + 3], sWi[(d + 3) * 32 + m], a3);
            }
            sPI[half * 32 + m] = (a0 + a1) + (a2 + a3);
        }
        __syncthreads();

        if (side) {
            // pack keTh pairs
            if (ltid < 48)
                g_keTh[((size_t)bb * 48 + ltid) * NK_ + n] =
                    pack2(sEQ[half * 96 + 2*ltid], sEQ[half * 96 + 2*ltid + 1]);
            // Bk[f] = ki @ W1[32:64]  (fp32 accumulate, pack fp16 pairs)
            if (ltid < 64) {
                float a0 = 0.f, a1 = 0.f;
                #pragma unroll
                for (int m = 0; m < 32; m++) {
                    const float kv = sPI[half * 32 + m];
                    a0 = fmaf(kv, sW1s[m * 128 + 2*ltid],     a0);
                    a1 = fmaf(kv, sW1s[m * 128 + 2*ltid + 1], a1);
                }
                g_Bkh[((size_t)bb * NK_ + n) * 64 + ltid] = pack2(a0, a1);
            }
        } else {
            if (ltid < 48)
                g_qeh[(size_t)r * 48 + ltid] =
                    pack2(sEQ[half * 96 + 2*ltid], sEQ[half * 96 + 2*ltid + 1]);
            // Aq[f] = b1 + qi @ W1[0:32]  (fp32 accumulate, pack fp16 pairs)
            if (ltid < 64) {
                float a0 = sB1[2*ltid], a1 = sB1[2*ltid + 1];
                #pragma unroll
                for (int m = 0; m < 32; m++) {
                    const float qv = sPI[half * 32 + m];
                    a0 = fmaf(qv, sW1s[m * 128 + 2*ltid],     a0);
                    a1 = fmaf(qv, sW1s[m * 128 + 2*ltid + 1], a1);
                }
                g_Aqh[(size_t)r * 64 + ltid] = pack2(a0, a1);
            }
        }
        __syncthreads();   // buffers reused next iteration
    }
}

// =====================================================================
// Kernel B: pairwise kernel, fragment-direct feats (fp16-packed inputs).
//   CTA = 16 q-rows x 64 k-rows; 8 passes of (2q x 64k, M=128).
//   GEMM1: A=[dot|dist] (K=64) @ W1h ; epi: +Aq +Bk, silu ; GEMM2 (K=128)
// =====================================================================
__global__ __launch_bounds__(256, 2)
void pair_kernel(const float* __restrict__ b2g, float* __restrict__ out)
{
    extern __shared__ char sm[];
    __half*   sW1h  = (__half*)(sm + O_W1H);
    __half*   sW2h  = (__half*)(sm + O_W2H);
    uint32_t* sKETH = (uint32_t*)(sm + O_KETH);
    uint32_t* sBKH  = (uint32_t*)(sm + O_BKH);
    uint32_t* sAQH  = (uint32_t*)(sm + O_AQH);
    uint32_t* sQEH  = (uint32_t*)(sm + O_QEH);
    float*    sB2   = (float*)(sm + O_B2);

    const int tid = threadIdx.x;
    const int b   = blockIdx.z;
    const int k0  = blockIdx.x * 64;
    const int q0  = blockIdx.y * 16;

    // ---------------- phase 0: one-time loads ----------------
    {   // pre-packed fp16 weights: W1h 1152 f4, W2h 1088 f4
        float4* d1 = (float4*)sW1h; const float4* s1 = (const float4*)g_W1h;
        for (int i = tid; i < 1152; i += 256) d1[i] = s1[i];
        float4* d2 = (float4*)sW2h; const float4* s2 = (const float4*)g_W2h;
        for (int i = tid; i < 1088; i += 256) d2[i] = s2[i];
    }
    {   // keTh: 48 rows x 16 uint4 (64 u32), smem stride 68 u32
        for (int i = tid; i < 768; i += 256) {
            const int row = i >> 4, c4 = i & 15;
            *(uint4*)(sKETH + row * 68 + c4 * 4) =
                *(const uint4*)(g_keTh + ((size_t)b * 48 + row) * NK_ + k0 + c4 * 4);
        }
    }
    {   // Bkh: 64 rows x 16 uint4 (64 u32), smem stride 68 u32
        for (int i = tid; i < 1024; i += 256) {
            const int row = i >> 4, c4 = i & 15;
            *(uint4*)(sBKH + row * 68 + c4 * 4) =
                *(const uint4*)(g_Bkh + ((size_t)b * NK_ + k0 + row) * 64 + c4 * 4);
        }
    }
    {   // qeh: 192 uint4 ; Aqh: 16 rows x 64 u32 = 256 uint4 (contiguous)
        for (int i = tid; i < 192; i += 256)
            ((uint4*)sQEH)[i] = *(const uint4*)(g_qeh + (size_t)(b * NQ_ + q0) * 48 + i * 4);
        for (int i = tid; i < 256; i += 256)
            ((uint4*)sAQH)[i] = *(const uint4*)(g_Aqh + (size_t)(b * NQ_ + q0) * 64 + i * 4);
        if (tid >= 192 && tid < 256) sB2[tid - 192] = b2g[tid - 192];
    }
    __syncthreads();   // the ONLY barrier

    // ---------------- warp/lane geometry ----------------
    const int wid = tid >> 5, lane = tid & 31;
    const int grp = lane >> 2, tig = lane & 3;
    const int kbase = (wid & 3) * 16;
    const int kk1 = kbase + grp, kk2 = kbase + grp + 8;
    const int qq  = wid >> 2;

    const uint32_t sW1b = smem_u32(sW1h);
    const uint32_t sW2b = smem_u32(sW2h);

    const int brow = (lane & 7) + ((lane >> 4) << 3);
    const int bkof = ((lane >> 3) & 1) * 16;

    // ---------------- pass loop: 8 x (2q x 64k), no barriers ----------------
    #pragma unroll 1
    for (int pass = 0; pass < 8; pass++) {
        const int qrow = pass * 2 + qq;

        // ---- feats directly into GEMM1 A-fragments (fp16-packed inputs) ----
        uint32_t aDot[2][4], aDist[2][4];
        {
            float dotv[2][8], d2v[2][8];
            #pragma unroll
            for (int jj = 0; jj < 4; jj++) {
                float dv00 = 0.f, dv01 = 0.f, dv10 = 0.f, dv11 = 0.f;
                float sv00 = 0.f, sv01 = 0.f, sv10 = 0.f, sv11 = 0.f;
                #pragma unroll
                for (int c = 0; c < 3; c++) {
                    const int ch2 = c * 16 + tig + 4 * jj;
                    const float2 q2 = unpack2(sQEH[qrow * 48 + ch2]);
                    const float2 k1 = unpack2(sKETH[ch2 * 68 + kk1]);
                    const float2 k2 = unpack2(sKETH[ch2 * 68 + kk2]);
                    dv00 = fmaf(q2.x, k1.x, dv00);
                    dv01 = fmaf(q2.y, k1.y, dv01);
                    dv10 = fmaf(q2.x, k2.x, dv10);
                    dv11 = fmaf(q2.y, k2.y, dv11);
                    float e;
                    e = q2.x - k1.x; sv00 = fmaf(e, e, sv00);
                    e = q2.y - k1.y; sv01 = fmaf(e, e, sv01);
                    e = q2.x - k2.x; sv10 = fmaf(e, e, sv10);
                    e = q2.y - k2.y; sv11 = fmaf(e, e, sv11);
                }
                dotv[0][2*jj] = dv00; dotv[0][2*jj+1] = dv01;
                dotv[1][2*jj] = dv10; dotv[1][2*jj+1] = dv11;
                d2v[0][2*jj]  = sv00; d2v[0][2*jj+1]  = sv01;
                d2v[1][2*jj]  = sv10; d2v[1][2*jj+1]  = sv11;
            }
            #pragma unroll
            for (int ks = 0; ks < 2; ks++) {
                aDot[ks][0] = pack2(dotv[0][ks*4+0], dotv[0][ks*4+1]);
                aDot[ks][1] = pack2(dotv[1][ks*4+0], dotv[1][ks*4+1]);
                aDot[ks][2] = pack2(dotv[0][ks*4+2], dotv[0][ks*4+3]);
                aDot[ks][3] = pack2(dotv[1][ks*4+2], dotv[1][ks*4+3]);
                aDist[ks][0] = pack2(sqrt_ap(d2v[0][ks*4+0]), sqrt_ap(d2v[0][ks*4+1]));
                aDist[ks][1] = pack2(sqrt_ap(d2v[1][ks*4+0]), sqrt_ap(d2v[1][ks*4+1]));
                aDist[ks][2] = pack2(sqrt_ap(d2v[0][ks*4+2]), sqrt_ap(d2v[0][ks*4+3]));
                aDist[ks][3] = pack2(sqrt_ap(d2v[1][ks*4+2]), sqrt_ap(d2v[1][ks*4+3]));
            }
        }

        // ---- GEMM1: D1[16x128] = A(K=64, from regs) @ W1h ----
        float c1[16][4];
        #pragma unroll
        for (int nt = 0; nt < 16; nt++)
            #pragma unroll
            for (int j = 0; j < 4; j++) c1[nt][j] = 0.f;

        #pragma unroll
        for (int ks = 0; ks < 4; ks++) {
            const uint32_t* A = (ks < 2) ? aDot[ks] : aDist[ks-2];
            #pragma unroll
            for (int np = 0; np < 8; np++) {
                uint32_t bb[4];
                ldmx4(bb, sW1b + (np * 16 + brow) * 144 + ks * 32 + bkof);
                mma16816(c1[np * 2 + 0], A, bb[0], bb[1]);
                mma16816(c1[np * 2 + 1], A, bb[2], bb[3]);
            }
        }

        // ---- epilogue 1 (regs): +Aq +Bk, silu -> GEMM2 A-fragments ----
        uint32_t a2[8][4];
        #pragma unroll
        for (int kt = 0; kt < 8; kt++) {
            #pragma unroll
            for (int hnt = 0; hnt < 2; hnt++) {
                const int nt = kt * 2 + hnt;
                const float2 aq  = unpack2(sAQH[qrow * 64 + nt * 4 + tig]);
                const float2 bk1 = unpack2(sBKH[kk1 * 68 + nt * 4 + tig]);
                const float2 bk2 = unpack2(sBKH[kk2 * 68 + nt * 4 + tig]);
                const float v0 = silu_f(c1[nt][0] + aq.x + bk1.x);
                const float v1 = silu_f(c1[nt][1] + aq.y + bk1.y);
                const float v2 = silu_f(c1[nt][2] + aq.x + bk2.x);
                const float v3 = silu_f(c1[nt][3] + aq.y + bk2.y);
                a2[kt][hnt * 2 + 0] = pack2(v0, v1);
                a2[kt][hnt * 2 + 1] = pack2(v2, v3);
            }
        }

        // ---- GEMM2: D2[16x64] = H[16x128] @ W2 (A from registers) ----
        float c2[8][4];
        #pragma unroll
        for (int nt = 0; nt < 8; nt++)
            #pragma unroll
            for (int j = 0; j < 4; j++) c2[nt][j] = 0.f;

        #pragma unroll
        for (int ks = 0; ks < 8; ks++) {
            #pragma unroll
            for (int np = 0; np < 4; np++) {
                uint32_t bb[4];
                ldmx4(bb, sW2b + (np * 16 + brow) * 272 + ks * 32 + bkof);
                mma16816(c2[np * 2 + 0], a2[ks], bb[0], bb[1]);
                mma16816(c2[np * 2 + 1], a2[ks], bb[2], bb[3]);
            }
        }

        // ---- epilogue 2: +b2, store ----
        {
            const int q = q0 + qrow;
            #pragma unroll
            for (int h = 0; h < 2; h++) {
                const int kk = kbase + grp + h * 8;
                const size_t base = ((size_t)(b * NQ_ + q) * NK_ + k0 + kk) * 64;
                #pragma unroll
                for (int nt = 0; nt < 8; nt++) {
                    const int f = nt * 8 + tig * 2;
                    float2 v;
                    v.x = c2[nt][h * 2 + 0] + sB2[f];
                    v.y = c2[nt][h * 2 + 1] + sB2[f + 1];
                    *(float2*)&out[base + f] = v;
                }
            }
        }
    }
}

// =====================================================================
extern "C" void kernel_launch(void* const* d_in, const int* in_sizes, int n_in,
                              void* d_out, int out_size)
{
    (void)in_sizes; (void)n_in; (void)out_size;
    const float* q_equi = (const float*)d_in[0];
    const float* q_inv  = (const float*)d_in[1];
    const float* k_equi = (const float*)d_in[2];
    const float* k_inv  = (const float*)d_in[3];
    const float* Wqi = (const float*)d_in[4];  const float* bqi = (const float*)d_in[5];
    const float* Wki = (const float*)d_in[6];  const float* bki = (const float*)d_in[7];
    const float* Wqe = (const float*)d_in[8];  const float* bqe = (const float*)d_in[9];
    const float* Wke = (const float*)d_in[10]; const float* bke = (const float*)d_in[11];
    const float* W1  = (const float*)d_in[12]; const float* b1  = (const float*)d_in[13];
    const float* W2  = (const float*)d_in[14]; const float* b2  = (const float*)d_in[15];
    float* out = (float*)d_out;

    cudaFuncSetAttribute(proj_kernel, cudaFuncAttributeMaxDynamicSharedMemorySize, PROJ_SMEM);
    cudaFuncSetAttribute(pair_kernel, cudaFuncAttributeMaxDynamicSharedMemorySize, SMEM_TOTAL);

    proj_kernel<<<dim3(192, 3), 256, PROJ_SMEM>>>(q_equi, q_inv, k_equi, k_inv,
                                                  Wqi, bqi, Wki, bki,
                                                  Wqe, bqe, Wke, bke, W1, b1, W2);
    pair_kernel<<<dim3(NK_ / 64, NQ_ / 16, B_), 256, SMEM_TOTAL>>>(b2, out);
}